// round 15
// baseline (speedup 1.0000x reference)
#include <cuda_runtime.h>
#include <cuda_bf16.h>
#include <math.h>

#define Bb  2
#define Cc  128
#define Hh  256
#define Ww  510
#define WFD 256
#define HWD 130560   /* 256*510 */
#define BCD 256      /* Bb*Cc */

typedef unsigned int u32;
typedef unsigned long long u64;

__device__ __forceinline__ u64 pk2(float lo, float hi) {
    u64 r; asm("mov.b64 %0,{%1,%2};" : "=l"(r) : "f"(lo), "f"(hi)); return r;
}
__device__ __forceinline__ float2 up2(u64 v) {
    float2 r; asm("mov.b64 {%0,%1},%2;" : "=f"(r.x), "=f"(r.y) : "l"(v)); return r;
}
__device__ __forceinline__ u64 ffma2(u64 a, u64 b, u64 c) {
    u64 d; asm("fma.rn.f32x2 %0,%1,%2,%3;" : "=l"(d) : "l"(a), "l"(b), "l"(c)); return d;
}

// ---- tensor-core helpers -------------------------------------------------
__device__ __forceinline__ void mma_bf16(float* c, const u32* a, const u32* b) {
    asm("mma.sync.aligned.m16n8k16.row.col.f32.bf16.bf16.f32 "
        "{%0,%1,%2,%3},{%4,%5,%6,%7},{%8,%9},{%0,%1,%2,%3};"
        : "+f"(c[0]), "+f"(c[1]), "+f"(c[2]), "+f"(c[3])
        : "r"(a[0]), "r"(a[1]), "r"(a[2]), "r"(a[3]), "r"(b[0]), "r"(b[1]));
}
__device__ __forceinline__ void ldmAT(u32* a, u32 addr) {
    asm volatile("ldmatrix.sync.aligned.m8n8.x4.trans.shared.b16 {%0,%1,%2,%3},[%4];"
        : "=r"(a[0]), "=r"(a[1]), "=r"(a[2]), "=r"(a[3]) : "r"(addr));
}
__device__ __forceinline__ void ldmBT(u32* b, u32 addr) {
    asm volatile("ldmatrix.sync.aligned.m8n8.x2.trans.shared.b16 {%0,%1},[%2];"
        : "=r"(b[0]), "=r"(b[1]) : "r"(addr));
}
__device__ __forceinline__ u32 smaddr(const void* p) {
    return (u32)__cvta_generic_to_shared(p);
}
__device__ __forceinline__ void bsplit2(float a, float b, u32& hi, u32& lo) {
    __nv_bfloat16 ha = __float2bfloat16(a), hb = __float2bfloat16(b);
    hi = (u32)__bfloat16_as_ushort(ha) | ((u32)__bfloat16_as_ushort(hb) << 16);
    float ra = a - __bfloat162float(ha), rb = b - __bfloat162float(hb);
    __nv_bfloat16 la = __float2bfloat16(ra), lb = __float2bfloat16(rb);
    lo = (u32)__bfloat16_as_ushort(la) | ((u32)__bfloat16_as_ushort(lb) << 16);
}

// ---------------- scratch ----------------
__device__ float  d_yg [(size_t)BCD * HWD];
__device__ float  d_yx [(size_t)BCD * HWD];
__device__ float2 d_Fg [(size_t)BCD * Hh * WFD];
__device__ float2 d_Fx [(size_t)BCD * Hh * WFD];
__device__ float2 d_Gg [(size_t)BCD * Hh * WFD];
__device__ float2 d_Gx [(size_t)BCD * Hh * WFD];
__device__ float2 d_Sb [(size_t)BCD * WFD * WFD];
__device__ float2 d_Tb [(size_t)BCD * Hh * WFD];
__device__ float  d_rb [(size_t)BCD * HWD];
__device__ float  d_rsq[BCD * Hh];
__device__ float  d_vp [(size_t)BCD * Hh * 64];
__device__ float2 d_W256[256];
// mma-fragment-order DFT tables
__device__ u64 d_DwFrh[32768], d_DwFrl[32768], d_DwFih[32768], d_DwFil[32768];
__device__ u64 d_CwF1h[32768], d_CwF1l[32768], d_CwF2h[32768], d_CwF2l[32768];
// conv weight A-fragment tables
__device__ u64 d_WF[2][4][2048];

__device__ __forceinline__ void sp_bits(float x, u32& hb, u32& lb) {
    __nv_bfloat16 h = __float2bfloat16(x);
    hb = (u32)__bfloat16_as_ushort(h);
    lb = (u32)__bfloat16_as_ushort(__float2bfloat16(x - __bfloat162float(h)));
}

// ---------------- table builder ----------------
__global__ void build_tables_kernel() {
    int idx = blockIdx.x * blockDim.x + threadIdx.x;
    int stride = gridDim.x * blockDim.x;
    float rsW = rsqrtf(510.0f);

    for (int i = idx; i < 32768; i += stride) {
        int lane = i & 31, kblk = (i >> 5) & 31, nblk = i >> 10;
        int v = nblk * 8 + (lane >> 2);
        u32 prh[2], prl[2], pih[2], pil[2];
#pragma unroll
        for (int reg = 0; reg < 2; reg++) {
            prh[reg] = prl[reg] = pih[reg] = pil[reg] = 0;
#pragma unroll
            for (int e = 0; e < 2; e++) {
                int w = kblk * 16 + (lane & 3) * 2 + e + reg * 8;
                float re = 0.f, im = 0.f;
                if (w < Ww) {
                    int m = (w * v) % Ww;
                    float s, c; sincospif(2.0f * (float)m / (float)Ww, &s, &c);
                    re = c * rsW; im = -s * rsW;
                }
                u32 hb, lb;
                sp_bits(re, hb, lb);
                prh[reg] |= hb << (16 * e); prl[reg] |= lb << (16 * e);
                sp_bits(im, hb, lb);
                pih[reg] |= hb << (16 * e); pil[reg] |= lb << (16 * e);
            }
        }
        d_DwFrh[i] = (u64)prh[0] | ((u64)prh[1] << 32);
        d_DwFrl[i] = (u64)prl[0] | ((u64)prl[1] << 32);
        d_DwFih[i] = (u64)pih[0] | ((u64)pih[1] << 32);
        d_DwFil[i] = (u64)pil[0] | ((u64)pil[1] << 32);
    }
    for (int i = idx; i < 32768; i += stride) {
        int lane = i & 31, kblk = (i >> 5) & 15, nblk = i >> 9;
        int w = nblk * 8 + (lane >> 2);
        u32 p1h[2], p1l[2], p2h[2], p2l[2];
#pragma unroll
        for (int reg = 0; reg < 2; reg++) {
            p1h[reg] = p1l[reg] = p2h[reg] = p2l[reg] = 0;
#pragma unroll
            for (int e = 0; e < 2; e++) {
                int v = kblk * 16 + (lane & 3) * 2 + e + reg * 8;
                float b1 = 0.f, b2 = 0.f;
                if (w < Ww) {
                    int m = (v * w) % Ww;
                    float s, c; sincospif(2.0f * (float)m / (float)Ww, &s, &c);
                    float sv = (v == 0 || v == 255) ? 1.0f : 2.0f;
                    b1 = sv * c * rsW; b2 = -sv * s * rsW;
                }
                u32 hb, lb;
                sp_bits(b1, hb, lb);
                p1h[reg] |= hb << (16 * e); p1l[reg] |= lb << (16 * e);
                sp_bits(b2, hb, lb);
                p2h[reg] |= hb << (16 * e); p2l[reg] |= lb << (16 * e);
            }
        }
        d_CwF1h[i] = (u64)p1h[0] | ((u64)p1h[1] << 32);
        d_CwF1l[i] = (u64)p1l[0] | ((u64)p1l[1] << 32);
        d_CwF2h[i] = (u64)p2h[0] | ((u64)p2h[1] << 32);
        d_CwF2l[i] = (u64)p2l[0] | ((u64)p2l[1] << 32);
    }
    for (int j = idx; j < 256; j += stride) {
        float s, c; sincospif(2.0f * (float)j / 256.0f, &s, &c);
        d_W256[j] = make_float2(c, -s);
    }
}

// ---------------- W pack ----------------
__global__ void pack_w_kernel(const float* __restrict__ wg, const float* __restrict__ wx) {
    int t = blockIdx.x * blockDim.x + threadIdx.x;
    if (t >= 4096) return;
    int wsel = t >> 11;
    int i = t & 2047;
    const float* W = wsel ? wx : wg;
    int lane = i & 31, kblk = (i >> 5) & 7, mblk = i >> 8;
    u32 qh[4], ql[4];
#pragma unroll
    for (int reg = 0; reg < 4; reg++) {
        int row = mblk * 16 + (lane >> 2) + 8 * (reg & 1);
        u32 hi = 0, lo = 0;
#pragma unroll
        for (int e = 0; e < 2; e++) {
            int k = kblk * 16 + (lane & 3) * 2 + e + 8 * (reg >> 1);
            float v = W[row * 128 + k];
            u32 hb, lb; sp_bits(v, hb, lb);
            hi |= hb << (16 * e); lo |= lb << (16 * e);
        }
        qh[reg] = hi; ql[reg] = lo;
    }
    d_WF[wsel][0][i] = (u64)qh[0] | ((u64)qh[1] << 32);
    d_WF[wsel][1][i] = (u64)ql[0] | ((u64)ql[1] << 32);
    d_WF[wsel][2][i] = (u64)qh[2] | ((u64)qh[3] << 32);
    d_WF[wsel][3][i] = (u64)ql[2] | ((u64)ql[3] << 32);
}

__device__ __forceinline__ float sigm(float v) { return 1.f / (1.f + expf(-v)); }

#define PITS 72
#define SSZ  (32 * PITS)

// ---------------- 1x1 conv — merged g/x launch ----------------
__global__ void __launch_bounds__(256, 2) conv_tc(
    const float* __restrict__ g, const float* __restrict__ x,
    const float* __restrict__ bg, const float* __restrict__ bx,
    float* __restrict__ yg, float* __restrict__ yx)
{
    __shared__ __nv_bfloat16 sXh[2][SSZ], sXl[2][SSZ];
    int z = blockIdx.z;
    int b = z & 1, wsel = z >> 1;
    const float* Xb = (wsel ? x : g) + (size_t)b * Cc * HWD;
    float* Yb = (wsel ? yx : yg) + (size_t)b * Cc * HWD;
    const float* bias = wsel ? bx : bg;
    int n0 = blockIdx.x * 64, m0 = blockIdx.y * 64;
    int t = threadIdx.x, lane = t & 31, wid = t >> 5;
    int wm = (wid >> 2) * 32, wn = (wid & 3) * 16;
    int g4 = lane >> 2, tc4 = lane & 3;

    float acc[2][2][4];
#pragma unroll
    for (int i = 0; i < 2; i++)
#pragma unroll
        for (int j = 0; j < 2; j++)
#pragma unroll
            for (int q = 0; q < 4; q++) acc[i][j][q] = 0.f;

    int kB = (lane & 7) + ((lane >> 3) & 1) * 8;
    int scB = t & 31, srB = t >> 5;
    int mblk_base = (m0 + wm) >> 4;

    float2 xv[4];
#define CONV_LOAD(K0) { \
    _Pragma("unroll") \
    for (int i = 0; i < 4; i++) \
        xv[i] = *(const float2*)&Xb[(size_t)((K0) + srB + i * 8) * HWD + n0 + 2 * scB]; }
#define CONV_STORE(BF) { \
    _Pragma("unroll") \
    for (int i = 0; i < 4; i++) { \
        u32 hi, lo; bsplit2(xv[i].x, xv[i].y, hi, lo); \
        int so = (srB + i * 8) * PITS + 2 * scB; \
        *(u32*)&sXh[BF][so] = hi; *(u32*)&sXl[BF][so] = lo; \
    } }

    CONV_LOAD(0)
    CONV_STORE(0)
    __syncthreads();
    for (int it = 0; it < 4; it++) {
        int buf = it & 1;
        if (it < 3) CONV_LOAD((it + 1) * 32)
        u32 aXh = smaddr(sXh[buf]), aXl = smaddr(sXl[buf]);
#pragma unroll
        for (int ks = 0; ks < 2; ks++) {
            int kb = ks * 16;
            int kblk = it * 2 + ks;
            u32 ah[2][4], al[2][4];
#pragma unroll
            for (int tm = 0; tm < 2; tm++) {
                size_t bi = ((size_t)((mblk_base + tm) * 8 + kblk) << 5) + lane;
                u64 v;
                v = d_WF[wsel][0][bi]; ah[tm][0] = (u32)v; ah[tm][1] = (u32)(v >> 32);
                v = d_WF[wsel][2][bi]; ah[tm][2] = (u32)v; ah[tm][3] = (u32)(v >> 32);
                v = d_WF[wsel][1][bi]; al[tm][0] = (u32)v; al[tm][1] = (u32)(v >> 32);
                v = d_WF[wsel][3][bi]; al[tm][2] = (u32)v; al[tm][3] = (u32)(v >> 32);
            }
            u32 bh[2][2], bl[2][2];
#pragma unroll
            for (int tn = 0; tn < 2; tn++) {
                u32 off = ((kb + kB) * PITS + wn + 8 * tn) * 2;
                ldmBT(bh[tn], aXh + off);
                ldmBT(bl[tn], aXl + off);
            }
#pragma unroll
            for (int tm = 0; tm < 2; tm++)
#pragma unroll
                for (int tn = 0; tn < 2; tn++) {
                    mma_bf16(acc[tm][tn], ah[tm], bh[tn]);
                    mma_bf16(acc[tm][tn], ah[tm], bl[tn]);
                    mma_bf16(acc[tm][tn], al[tm], bh[tn]);
                }
        }
        if (it < 3) CONV_STORE(buf ^ 1)
        __syncthreads();
    }
#undef CONV_LOAD
#undef CONV_STORE
#pragma unroll
    for (int tm = 0; tm < 2; tm++)
#pragma unroll
        for (int tn = 0; tn < 2; tn++) {
            int r0 = m0 + wm + 16 * tm + g4;
            int col = n0 + wn + 8 * tn + 2 * tc4;
            float bv0 = bias[r0], bv1 = bias[r0 + 8];
            *(float2*)&Yb[(size_t)r0 * HWD + col] =
                make_float2(acc[tm][tn][0] + bv0, acc[tm][tn][1] + bv0);
            *(float2*)&Yb[(size_t)(r0 + 8) * HWD + col] =
                make_float2(acc[tm][tn][2] + bv1, acc[tm][tn][3] + bv1);
        }
}

// ------- rfft along W — fragment-direct A and B, no smem, no barriers -------
__global__ void __launch_bounds__(256, 2) rfftw_tc(
    const float* __restrict__ yg, const float* __restrict__ yx,
    float2* __restrict__ Fg, float2* __restrict__ Fx)
{
    int z = blockIdx.z;
    int sel = z >> 8, bc = z & 255;
    const float* A = (sel ? yx : yg) + (size_t)bc * HWD;
    float2* Cp = (sel ? Fx : Fg) + (size_t)bc * Hh * WFD;
    int n0 = blockIdx.x * 64, m0 = blockIdx.y * 64;
    int t = threadIdx.x, lane = t & 31, wid = t >> 5;
    int wm = (wid >> 2) * 32, wn = (wid & 3) * 16;
    int g = lane >> 2, tc = lane & 3;

    float cre[2][2][4], cim[2][2][4];
#pragma unroll
    for (int i = 0; i < 2; i++)
#pragma unroll
        for (int j = 0; j < 2; j++)
#pragma unroll
            for (int q = 0; q < 4; q++) { cre[i][j][q] = 0.f; cim[i][j][q] = 0.f; }

    int nblk0 = (n0 + wn) >> 3;
    int rA = m0 + wm + g;          // + 16*tm, +8
    int cA = tc * 2;               // + kblk*16, +8

    for (int kblk = 0; kblk < 32; kblk++) {
        int c0 = kblk * 16 + cA;
        int c2 = c0 + 8;
        u32 ah[2][4], al[2][4];
#pragma unroll
        for (int tm = 0; tm < 2; tm++) {
            const float* rp0 = A + (size_t)(rA + 16 * tm) * Ww;
            const float* rp1 = rp0 + (size_t)8 * Ww;
            float2 v0 = *(const float2*)&rp0[c0];
            float2 v1 = *(const float2*)&rp1[c0];
            float2 v2 = (c2 < Ww) ? *(const float2*)&rp0[c2] : make_float2(0.f, 0.f);
            float2 v3 = (c2 < Ww) ? *(const float2*)&rp1[c2] : make_float2(0.f, 0.f);
            bsplit2(v0.x, v0.y, ah[tm][0], al[tm][0]);
            bsplit2(v1.x, v1.y, ah[tm][1], al[tm][1]);
            bsplit2(v2.x, v2.y, ah[tm][2], al[tm][2]);
            bsplit2(v3.x, v3.y, ah[tm][3], al[tm][3]);
        }
        u32 brh[2][2], brl[2][2], bih[2][2], bil[2][2];
#pragma unroll
        for (int tn = 0; tn < 2; tn++) {
            size_t bi = ((size_t)((nblk0 + tn) * 32 + kblk) << 5) + lane;
            u64 v;
            v = d_DwFrh[bi]; brh[tn][0] = (u32)v; brh[tn][1] = (u32)(v >> 32);
            v = d_DwFrl[bi]; brl[tn][0] = (u32)v; brl[tn][1] = (u32)(v >> 32);
            v = d_DwFih[bi]; bih[tn][0] = (u32)v; bih[tn][1] = (u32)(v >> 32);
            v = d_DwFil[bi]; bil[tn][0] = (u32)v; bil[tn][1] = (u32)(v >> 32);
        }
#pragma unroll
        for (int tm = 0; tm < 2; tm++)
#pragma unroll
            for (int tn = 0; tn < 2; tn++) {
                mma_bf16(cre[tm][tn], ah[tm], brh[tn]);
                mma_bf16(cre[tm][tn], ah[tm], brl[tn]);
                mma_bf16(cre[tm][tn], al[tm], brh[tn]);
                mma_bf16(cim[tm][tn], ah[tm], bih[tn]);
                mma_bf16(cim[tm][tn], ah[tm], bil[tn]);
                mma_bf16(cim[tm][tn], al[tm], bih[tn]);
            }
    }
#pragma unroll
    for (int tm = 0; tm < 2; tm++)
#pragma unroll
        for (int tn = 0; tn < 2; tn++) {
            int r0 = m0 + wm + 16 * tm + g;
            int col = n0 + wn + 8 * tn + 2 * tc;
            float4 v0 = make_float4(cre[tm][tn][0], cim[tm][tn][0], cre[tm][tn][1], cim[tm][tn][1]);
            *(float4*)&Cp[(size_t)r0 * WFD + col] = v0;
            float4 v1 = make_float4(cre[tm][tn][2], cim[tm][tn][2], cre[tm][tn][3], cim[tm][tn][3]);
            *(float4*)&Cp[(size_t)(r0 + 8) * WFD + col] = v1;
        }
}

// ------- irfft along W + residual — fragment-direct, no smem/barriers -------
__global__ void __launch_bounds__(256, 2) irfft_add_tc(
    const float2* __restrict__ T, const float* __restrict__ x, float* __restrict__ r)
{
    int bc = blockIdx.z;
    const float2* Ap = T + (size_t)bc * 65536;
    int n0 = blockIdx.x * 64, m0 = blockIdx.y * 64;
    int t = threadIdx.x, lane = t & 31, wid = t >> 5;
    int wm = (wid >> 2) * 32, wn = (wid & 3) * 16;
    int g = lane >> 2, tc = lane & 3;

    float acc[2][2][4];
#pragma unroll
    for (int i = 0; i < 2; i++)
#pragma unroll
        for (int j = 0; j < 2; j++)
#pragma unroll
            for (int q = 0; q < 4; q++) acc[i][j][q] = 0.f;

    int nblk0 = (n0 + wn) >> 3;
    int rA = m0 + wm + g;
    int cA = tc * 2;

    for (int kblk = 0; kblk < 16; kblk++) {
        int k0 = kblk * 16 + cA;
        u32 arh[2][4], arl[2][4], aih[2][4], ail[2][4];
#pragma unroll
        for (int tm = 0; tm < 2; tm++) {
            const float2* rp0 = Ap + (size_t)(rA + 16 * tm) * 256;
            const float2* rp1 = rp0 + 8 * 256;
            float4 v0 = *(const float4*)&rp0[k0];
            float4 v1 = *(const float4*)&rp1[k0];
            float4 v2 = *(const float4*)&rp0[k0 + 8];
            float4 v3 = *(const float4*)&rp1[k0 + 8];
            bsplit2(v0.x, v0.z, arh[tm][0], arl[tm][0]);
            bsplit2(v0.y, v0.w, aih[tm][0], ail[tm][0]);
            bsplit2(v1.x, v1.z, arh[tm][1], arl[tm][1]);
            bsplit2(v1.y, v1.w, aih[tm][1], ail[tm][1]);
            bsplit2(v2.x, v2.z, arh[tm][2], arl[tm][2]);
            bsplit2(v2.y, v2.w, aih[tm][2], ail[tm][2]);
            bsplit2(v3.x, v3.z, arh[tm][3], arl[tm][3]);
            bsplit2(v3.y, v3.w, aih[tm][3], ail[tm][3]);
        }
        u32 b1h[2][2], b1l[2][2], b2h[2][2], b2l[2][2];
#pragma unroll
        for (int tn = 0; tn < 2; tn++) {
            size_t bi = ((size_t)((nblk0 + tn) * 16 + kblk) << 5) + lane;
            u64 v;
            v = d_CwF1h[bi]; b1h[tn][0] = (u32)v; b1h[tn][1] = (u32)(v >> 32);
            v = d_CwF1l[bi]; b1l[tn][0] = (u32)v; b1l[tn][1] = (u32)(v >> 32);
            v = d_CwF2h[bi]; b2h[tn][0] = (u32)v; b2h[tn][1] = (u32)(v >> 32);
            v = d_CwF2l[bi]; b2l[tn][0] = (u32)v; b2l[tn][1] = (u32)(v >> 32);
        }
#pragma unroll
        for (int tm = 0; tm < 2; tm++)
#pragma unroll
            for (int tn = 0; tn < 2; tn++) {
                mma_bf16(acc[tm][tn], arh[tm], b1h[tn]);
                mma_bf16(acc[tm][tn], arh[tm], b1l[tn]);
                mma_bf16(acc[tm][tn], arl[tm], b1h[tn]);
                mma_bf16(acc[tm][tn], aih[tm], b2h[tn]);
                mma_bf16(acc[tm][tn], aih[tm], b2l[tn]);
                mma_bf16(acc[tm][tn], ail[tm], b2h[tn]);
            }
    }
#pragma unroll
    for (int tm = 0; tm < 2; tm++)
#pragma unroll
        for (int tn = 0; tn < 2; tn++) {
            int col = n0 + wn + 8 * tn + 2 * tc;
            if (col < Ww) {
                int r0 = m0 + wm + 16 * tm + g;
                size_t i0 = (size_t)bc * HWD + (size_t)r0 * Ww + col;
                size_t i1 = i0 + (size_t)8 * Ww;
                float2 xv = *(const float2*)&x[i0];
                *(float2*)&r[i0] = make_float2(acc[tm][tn][0] + xv.x, acc[tm][tn][1] + xv.y);
                xv = *(const float2*)&x[i1];
                *(float2*)&r[i1] = make_float2(acc[tm][tn][2] + xv.x, acc[tm][tn][3] + xv.y);
            }
        }
}

// ---------------- forward ffth (merged g/x) + fused variance partials ------
__global__ void __launch_bounds__(256) ffth_fwd(
    const float2* __restrict__ Fg, const float2* __restrict__ Fx,
    float2* __restrict__ Gg, float2* __restrict__ Gx,
    const float2* __restrict__ fg, const float2* __restrict__ fx,
    float* __restrict__ vp)
{
    __shared__ float2 Xs[256][17];
    __shared__ float2 Ws[256];
    int yz = blockIdx.y;
    int sel = yz >> 8, bc = yz & 255;
    const float2* inp = (sel ? Fx : Fg) + (size_t)bc * 65536;
    float2* outp = (sel ? Gx : Gg) + (size_t)bc * 65536;
    const float2* filt = sel ? fx : fg;
    int v0 = blockIdx.x * 16;
    int tx = threadIdx.x;
    int ty = threadIdx.y;
    int t = ty * 16 + tx;

    {
        float2 w = d_W256[t];
        Ws[t] = w;
    }
#pragma unroll
    for (int i = 0; i < 16; i++) {
        int h = i * 16 + ty;
        Xs[h][tx] = inp[(size_t)h * 256 + v0 + tx];
    }
    __syncthreads();

    float2 rr[16];
    {
        u64 tw[16];
#pragma unroll
        for (int n1 = 0; n1 < 16; n1++) {
            float2 w = Ws[(n1 * ty * 16) & 255];
            tw[n1] = pk2(w.x, w.y);
        }
#pragma unroll
        for (int n2 = 0; n2 < 16; n2++) {
            u64 accA = 0ull, accB = 0ull;
#pragma unroll
            for (int n1 = 0; n1 < 16; n1++) {
                float2 xv = Xs[16 * n1 + n2][tx];
                u64 xp = pk2(xv.x, xv.y);
                u64 xq = pk2(xv.y, xv.x);
                accA = ffma2(xp, tw[n1], accA);
                accB = ffma2(xq, tw[n1], accB);
            }
            float2 a = up2(accA), b = up2(accB);
            float ar = a.x - a.y, ai = b.x + b.y;
            float2 tm = Ws[(n2 * ty) & 255];
            rr[n2] = make_float2(ar * tm.x - ai * tm.y, ar * tm.y + ai * tm.x);
        }
    }
    __syncthreads();
#pragma unroll
    for (int n2 = 0; n2 < 16; n2++)
        Xs[ty * 16 + n2][tx] = rr[n2];
    __syncthreads();

    {
        u64 tw[16];
#pragma unroll
        for (int n2 = 0; n2 < 16; n2++) {
            float2 w = Ws[(n2 * ty * 16) & 255];
            tw[n2] = pk2(w.x, w.y);
        }
        int c = bc & (Cc - 1);
#pragma unroll
        for (int k1 = 0; k1 < 16; k1++) {
            u64 accA = 0ull, accB = 0ull;
#pragma unroll
            for (int n2 = 0; n2 < 16; n2++) {
                float2 xv = Xs[k1 * 16 + n2][tx];
                u64 xp = pk2(xv.x, xv.y);
                u64 xq = pk2(xv.y, xv.x);
                accA = ffma2(xp, tw[n2], accA);
                accB = ffma2(xq, tw[n2], accB);
            }
            float2 a = up2(accA), b = up2(accB);
            int u = k1 + 16 * ty;
            float2 v = make_float2((a.x - a.y) * 0.0625f, (b.x + b.y) * 0.0625f);
            float2 wc = filt[((size_t)c * Hh + u) * WFD + v0 + tx];
            v = make_float2(v.x * wc.x - v.y * wc.y, v.x * wc.y + v.y * wc.x);
            outp[(size_t)u * 256 + v0 + tx] = v;
            if (sel == 0) {
                float sre = v.x, sim = v.y, ssq = v.x * v.x + v.y * v.y;
#pragma unroll
                for (int msk = 8; msk >= 1; msk >>= 1) {
                    sre += __shfl_xor_sync(0xFFFFFFFFu, sre, msk);
                    sim += __shfl_xor_sync(0xFFFFFFFFu, sim, msk);
                    ssq += __shfl_xor_sync(0xFFFFFFFFu, ssq, msk);
                }
                if (tx == 0) {
                    size_t idx = (((size_t)bc * 256 + u) * 16 + blockIdx.x) * 4;
                    *(float4*)&vp[idx] = make_float4(sre, sim, ssq, 0.f);
                }
            }
        }
    }
}

// ------- variance finalize -------
__global__ void var_fin(const float* __restrict__ vp, float* __restrict__ rsq)
{
    int row = blockIdx.x * 256 + threadIdx.x;
    const float4* p = (const float4*)(vp + (size_t)row * 64);
    float sre = 0.f, sim = 0.f, ssq = 0.f;
#pragma unroll
    for (int i = 0; i < 16; i++) {
        float4 v = p[i];
        sre += v.x; sim += v.y; ssq += v.z;
    }
    float mr = sre * (1.f / 256.f), mi = sim * (1.f / 256.f);
    float var = ssq * (1.f / 256.f) - mr * mr - mi * mi;
    rsq[row] = 1.f / sqrtf(6.283185307179586f * var);
}

// ---------------- inverse ffth ----------------
__global__ void __launch_bounds__(256) ffth_inv(
    const float2* __restrict__ in, float2* __restrict__ out)
{
    __shared__ float2 Xs[256][17];
    __shared__ float2 Ws[256];
    int bc = blockIdx.y;
    int v0 = blockIdx.x * 16;
    int tx = threadIdx.x;
    int ty = threadIdx.y;
    int t = ty * 16 + tx;
    const float2* inp = in + (size_t)bc * 65536 + v0;
    float2* outp = out + (size_t)bc * 65536 + v0;

    {
        float2 w = d_W256[t];
        w.y = -w.y;
        Ws[t] = w;
    }
#pragma unroll
    for (int i = 0; i < 16; i++) {
        int h = i * 16 + ty;
        Xs[h][tx] = inp[(size_t)h * 256 + tx];
    }
    __syncthreads();

    float2 rr[16];
    {
        u64 tw[16];
#pragma unroll
        for (int n1 = 0; n1 < 16; n1++) {
            float2 w = Ws[(n1 * ty * 16) & 255];
            tw[n1] = pk2(w.x, w.y);
        }
#pragma unroll
        for (int n2 = 0; n2 < 16; n2++) {
            u64 accA = 0ull, accB = 0ull;
#pragma unroll
            for (int n1 = 0; n1 < 16; n1++) {
                float2 xv = Xs[16 * n1 + n2][tx];
                u64 xp = pk2(xv.x, xv.y);
                u64 xq = pk2(xv.y, xv.x);
                accA = ffma2(xp, tw[n1], accA);
                accB = ffma2(xq, tw[n1], accB);
            }
            float2 a = up2(accA), b = up2(accB);
            float ar = a.x - a.y, ai = b.x + b.y;
            float2 tm = Ws[(n2 * ty) & 255];
            rr[n2] = make_float2(ar * tm.x - ai * tm.y, ar * tm.y + ai * tm.x);
        }
    }
    __syncthreads();
#pragma unroll
    for (int n2 = 0; n2 < 16; n2++)
        Xs[ty * 16 + n2][tx] = rr[n2];
    __syncthreads();

    {
        u64 tw[16];
#pragma unroll
        for (int n2 = 0; n2 < 16; n2++) {
            float2 w = Ws[(n2 * ty * 16) & 255];
            tw[n2] = pk2(w.x, w.y);
        }
#pragma unroll
        for (int k1 = 0; k1 < 16; k1++) {
            u64 accA = 0ull, accB = 0ull;
#pragma unroll
            for (int n2 = 0; n2 < 16; n2++) {
                float2 xv = Xs[k1 * 16 + n2][tx];
                u64 xp = pk2(xv.x, xv.y);
                u64 xq = pk2(xv.y, xv.x);
                accA = ffma2(xp, tw[n2], accA);
                accB = ffma2(xq, tw[n2], accB);
            }
            float2 a = up2(accA), b = up2(accB);
            int u = k1 + 16 * ty;
            float2 v = make_float2((a.x - a.y) * 0.0625f, (b.x + b.y) * 0.0625f);
            outp[(size_t)u * 256 + tx] = v;
        }
    }
}

// ------- scores — HMMA complex, double-buffered (dynamic smem) -------
__global__ void __launch_bounds__(256) scores_tc(
    const float2* __restrict__ Gb, const float2* __restrict__ Xb,
    const float* __restrict__ rsq, float2* __restrict__ Sb)
{
    extern __shared__ __nv_bfloat16 dynS[];
    __nv_bfloat16* sGrh = dynS;
    __nv_bfloat16* sGrl = sGrh + 2 * SSZ;
    __nv_bfloat16* sGih = sGrl + 2 * SSZ;
    __nv_bfloat16* sGil = sGih + 2 * SSZ;
    __nv_bfloat16* sXrh = sGil + 2 * SSZ;
    __nv_bfloat16* sXrl = sXrh + 2 * SSZ;
    __nv_bfloat16* sXih = sXrl + 2 * SSZ;
    __nv_bfloat16* sXil = sXih + 2 * SSZ;
    int bc = blockIdx.z;
    const float2* Ap = Gb + (size_t)bc * 65536;
    const float2* Bp = Xb + (size_t)bc * 65536;
    float2* Cp = Sb + (size_t)bc * 65536;
    int n0 = blockIdx.x * 64, m0 = blockIdx.y * 64;
    int t = threadIdx.x, lane = t & 31, wid = t >> 5;
    int wm = (wid >> 2) * 32, wn = (wid & 3) * 16;
    int g = lane >> 2, tc4 = lane & 3;

    float are[2][2][4], aim[2][2][4];
#pragma unroll
    for (int i = 0; i < 2; i++)
#pragma unroll
        for (int j = 0; j < 2; j++)
#pragma unroll
            for (int q = 0; q < 4; q++) { are[i][j][q] = 0.f; aim[i][j][q] = 0.f; }

    int kA = (lane & 7) + ((lane >> 4) & 1) * 8;
    int mA = ((lane >> 3) & 1) * 8;
    int kB = (lane & 7) + ((lane >> 3) & 1) * 8;
    int sc = t & 31, sr = t >> 5;

    float4 vA[4], vB[4];
#define SCR_LOAD(K0) { \
    _Pragma("unroll") \
    for (int i = 0; i < 4; i++) { \
        int k = sr + i * 8; \
        vA[i] = *(const float4*)&Ap[(size_t)((K0) + k) * 256 + m0 + 2 * sc]; \
        vB[i] = *(const float4*)&Bp[(size_t)((K0) + k) * 256 + n0 + 2 * sc]; \
    } }
#define SCR_STORE(BF) { \
    _Pragma("unroll") \
    for (int i = 0; i < 4; i++) { \
        int so = (BF) * SSZ + (sr + i * 8) * PITS + 2 * sc; \
        u32 hi, lo; \
        bsplit2(vA[i].x, vA[i].z, hi, lo); *(u32*)&sGrh[so] = hi; *(u32*)&sGrl[so] = lo; \
        bsplit2(vA[i].y, vA[i].w, hi, lo); *(u32*)&sGih[so] = hi; *(u32*)&sGil[so] = lo; \
        bsplit2(vB[i].x, vB[i].z, hi, lo); *(u32*)&sXrh[so] = hi; *(u32*)&sXrl[so] = lo; \
        bsplit2(vB[i].y, vB[i].w, hi, lo); *(u32*)&sXih[so] = hi; *(u32*)&sXil[so] = lo; \
    } }

    SCR_LOAD(0)
    SCR_STORE(0)
    __syncthreads();
    for (int it = 0; it < 8; it++) {
        int buf = it & 1;
        if (it < 7) SCR_LOAD((it + 1) * 32)
        u32 aGrh = smaddr(sGrh + buf * SSZ), aGrl = smaddr(sGrl + buf * SSZ);
        u32 aGih = smaddr(sGih + buf * SSZ), aGil = smaddr(sGil + buf * SSZ);
        u32 aXrh = smaddr(sXrh + buf * SSZ), aXrl = smaddr(sXrl + buf * SSZ);
        u32 aXih = smaddr(sXih + buf * SSZ), aXil = smaddr(sXil + buf * SSZ);
#pragma unroll
        for (int ks = 0; ks < 2; ks++) {
            int kb = ks * 16;
            u32 grh[2][4], grl[2][4], gih[2][4], gil[2][4];
#pragma unroll
            for (int tm = 0; tm < 2; tm++) {
                u32 off = ((kb + kA) * PITS + wm + 16 * tm + mA) * 2;
                ldmAT(grh[tm], aGrh + off);
                ldmAT(grl[tm], aGrl + off);
                ldmAT(gih[tm], aGih + off);
                ldmAT(gil[tm], aGil + off);
            }
            u32 xrh[2][2], xrl[2][2], xih[2][2], xil[2][2];
#pragma unroll
            for (int tn = 0; tn < 2; tn++) {
                u32 off = ((kb + kB) * PITS + wn + 8 * tn) * 2;
                ldmBT(xrh[tn], aXrh + off);
                ldmBT(xrl[tn], aXrl + off);
                ldmBT(xih[tn], aXih + off);
                ldmBT(xil[tn], aXil + off);
            }
#pragma unroll
            for (int tm = 0; tm < 2; tm++) {
                u32 nih[4], nil_[4];
#pragma unroll
                for (int q = 0; q < 4; q++) {
                    nih[q]  = gih[tm][q] ^ 0x80008000u;
                    nil_[q] = gil[tm][q] ^ 0x80008000u;
                }
#pragma unroll
                for (int tn = 0; tn < 2; tn++) {
                    mma_bf16(are[tm][tn], grh[tm], xrh[tn]);
                    mma_bf16(are[tm][tn], grh[tm], xrl[tn]);
                    mma_bf16(are[tm][tn], grl[tm], xrh[tn]);
                    mma_bf16(are[tm][tn], nih,     xih[tn]);
                    mma_bf16(are[tm][tn], nih,     xil[tn]);
                    mma_bf16(are[tm][tn], nil_,    xih[tn]);
                    mma_bf16(aim[tm][tn], grh[tm], xih[tn]);
                    mma_bf16(aim[tm][tn], grh[tm], xil[tn]);
                    mma_bf16(aim[tm][tn], grl[tm], xih[tn]);
                    mma_bf16(aim[tm][tn], gih[tm], xrh[tn]);
                    mma_bf16(aim[tm][tn], gih[tm], xrl[tn]);
                    mma_bf16(aim[tm][tn], gil[tm], xrh[tn]);
                }
            }
        }
        if (it < 7) SCR_STORE(buf ^ 1)
        __syncthreads();
    }
#undef SCR_LOAD
#undef SCR_STORE
#pragma unroll
    for (int tm = 0; tm < 2; tm++)
#pragma unroll
        for (int tn = 0; tn < 2; tn++) {
            int r0 = m0 + wm + 16 * tm + g;
            int col = n0 + wn + 8 * tn + 2 * tc4;
            float s0 = rsq[bc * Hh + r0], s1 = rsq[bc * Hh + r0 + 8];
            float4 o0 = make_float4(
                sigm(are[tm][tn][0] * s0), sigm(aim[tm][tn][0] * s0),
                sigm(are[tm][tn][1] * s0), sigm(aim[tm][tn][1] * s0));
            *(float4*)&Cp[(size_t)r0 * 256 + col] = o0;
            float4 o1 = make_float4(
                sigm(are[tm][tn][2] * s1), sigm(aim[tm][tn][2] * s1),
                sigm(are[tm][tn][3] * s1), sigm(aim[tm][tn][3] * s1));
            *(float4*)&Cp[(size_t)(r0 + 8) * 256 + col] = o1;
        }
}

// ------- channel LayerNorm — float4 smem-tiled -------
#define LN_SMEM ((128 * 32 + 2 * 8 * 32 + 64) * 16)
__global__ void __launch_bounds__(256) ln_kernel(
    const float* __restrict__ r, const float* __restrict__ gamma,
    const float* __restrict__ beta, float* __restrict__ out)
{
    extern __shared__ float4 lns[];
    float4* tile = lns;
    float4* ps   = tile + 128 * 32;
    float4* qs   = ps + 8 * 32;
    float4* muv  = qs + 8 * 32;
    float4* invv = muv + 32;
    int blk = blockIdx.x;
    int b = blk / 1020;
    int w0 = (blk - b * 1020) * 128;
    int t = threadIdx.x;
    int w4 = t & 31, cq = t >> 5;

    float4 s = make_float4(0.f, 0.f, 0.f, 0.f);
    float4 q = make_float4(0.f, 0.f, 0.f, 0.f);
#pragma unroll
    for (int c0 = 0; c0 < 128; c0 += 8) {
        int c = c0 + cq;
        float4 v = *(const float4*)&r[(size_t)(b * Cc + c) * HWD + w0 + w4 * 4];
        tile[c * 32 + w4] = v;
        s.x += v.x; s.y += v.y; s.z += v.z; s.w += v.w;
        q.x += v.x * v.x; q.y += v.y * v.y; q.z += v.z * v.z; q.w += v.w * v.w;
    }
    ps[cq * 32 + w4] = s;
    qs[cq * 32 + w4] = q;
    __syncthreads();
    if (t < 32) {
        float4 S = make_float4(0.f, 0.f, 0.f, 0.f);
        float4 Q = make_float4(0.f, 0.f, 0.f, 0.f);
#pragma unroll
        for (int i = 0; i < 8; i++) {
            float4 a = ps[i * 32 + t];
            S.x += a.x; S.y += a.y; S.z += a.z; S.w += a.w;
            a = qs[i * 32 + t];
            Q.x += a.x; Q.y += a.y; Q.z += a.z; Q.w += a.w;
        }
        float4 m = make_float4(S.x * (1.f / 128.f), S.y * (1.f / 128.f),
                               S.z * (1.f / 128.f), S.w * (1.f / 128.f));
        float4 iv;
        iv.x = rsqrtf(Q.x * (1.f / 128.f) - m.x * m.x + 1e-6f);
        iv.y = rsqrtf(Q.y * (1.f / 128.f) - m.y * m.y + 1e-6f);
        iv.z = rsqrtf(Q.z * (1.f / 128.f) - m.z * m.z + 1e-6f);
        iv.w = rsqrtf(Q.w * (1.f / 128.f) - m.w * m.w + 1e-6f);
        muv[t] = m;
        invv[t] = iv;
    }
    __syncthreads();
    float4 m = muv[w4], iv = invv[w4];
#pragma unroll
    for (int c0 = 0; c0 < 128; c0 += 8) {
        int c = c0 + cq;
        float4 v = tile[c * 32 + w4];
        float gm = gamma[c], bt = beta[c];
        float4 o;
        o.x = gm * (v.x - m.x) * iv.x + bt;
        o.y = gm * (v.y - m.y) * iv.y + bt;
        o.z = gm * (v.z - m.z) * iv.z + bt;
        o.w = gm * (v.w - m.w) * iv.w + bt;
        *(float4*)&out[(size_t)(b * Cc + c) * HWD + w0 + w4 * 4] = o;
    }
}

// ---------------- launch ----------------
extern "C" void kernel_launch(void* const* d_in, const int* in_sizes, int n_in,
                              void* d_out, int out_size)
{
    (void)in_sizes; (void)n_in; (void)out_size;
    const float*  g     = (const float*)d_in[0];
    const float*  x     = (const float*)d_in[1];
    const float*  wg    = (const float*)d_in[2];
    const float*  bg    = (const float*)d_in[3];
    const float*  wx    = (const float*)d_in[4];
    const float*  bx    = (const float*)d_in[5];
    const float2* fg    = (const float2*)d_in[6];
    const float2* fx    = (const float2*)d_in[7];
    const float*  gamma = (const float*)d_in[8];
    const float*  beta  = (const float*)d_in[9];
    float* out = (float*)d_out;

    float *yg, *yx, *rb, *rsq, *vp;
    float2 *Fg, *Fx, *Gg, *Gx, *S, *T;
    cudaGetSymbolAddress((void**)&yg,  d_yg);
    cudaGetSymbolAddress((void**)&yx,  d_yx);
    cudaGetSymbolAddress((void**)&Fg,  d_Fg);
    cudaGetSymbolAddress((void**)&Fx,  d_Fx);
    cudaGetSymbolAddress((void**)&Gg,  d_Gg);
    cudaGetSymbolAddress((void**)&Gx,  d_Gx);
    cudaGetSymbolAddress((void**)&S,   d_Sb);
    cudaGetSymbolAddress((void**)&T,   d_Tb);
    cudaGetSymbolAddress((void**)&rb,  d_rb);
    cudaGetSymbolAddress((void**)&rsq, d_rsq);
    cudaGetSymbolAddress((void**)&vp,  d_vp);

    static int attr_done = 0;
    if (!attr_done) {
        cudaFuncSetAttribute(scores_tc, cudaFuncAttributeMaxDynamicSharedMemorySize,
                             16 * SSZ * 2);
        cudaFuncSetAttribute(ln_kernel, cudaFuncAttributeMaxDynamicSharedMemorySize,
                             LN_SMEM);
        attr_done = 1;
    }

    dim3 blk(16, 16);

    build_tables_kernel<<<512, 256>>>();
    pack_w_kernel<<<16, 256>>>(wg, wx);

    conv_tc<<<dim3(HWD / 64, 2, 2 * Bb), 256>>>(g, x, bg, bx, yg, yx);

    rfftw_tc<<<dim3(4, 4, 2 * BCD), 256>>>(yg, yx, Fg, Fx);

    ffth_fwd<<<dim3(16, 2 * BCD), blk>>>(Fg, Fx, Gg, Gx, fg, fx, vp);

    var_fin<<<BCD * Hh / 256, 256>>>(vp, rsq);

    scores_tc<<<dim3(4, 4, BCD), 256, 16 * SSZ * 2>>>(Gg, Gx, rsq, S);

    ffth_inv<<<dim3(16, BCD), blk>>>(S, T);

    irfft_add_tc<<<dim3(8, 4, BCD), 256>>>(T, x, rb);

    ln_kernel<<<Bb * 1020, 256, LN_SMEM>>>(rb, gamma, beta, out);
}

// round 16
// speedup vs baseline: 1.1188x; 1.1188x over previous
#include <cuda_runtime.h>
#include <cuda_bf16.h>
#include <math.h>

#define Bb  2
#define Cc  128
#define Hh  256
#define Ww  510
#define WFD 256
#define HWD 130560   /* 256*510 */
#define BCD 256      /* Bb*Cc */

typedef unsigned int u32;
typedef unsigned long long u64;

__device__ __forceinline__ u64 pk2(float lo, float hi) {
    u64 r; asm("mov.b64 %0,{%1,%2};" : "=l"(r) : "f"(lo), "f"(hi)); return r;
}
__device__ __forceinline__ float2 up2(u64 v) {
    float2 r; asm("mov.b64 {%0,%1},%2;" : "=f"(r.x), "=f"(r.y) : "l"(v)); return r;
}
__device__ __forceinline__ u64 ffma2(u64 a, u64 b, u64 c) {
    u64 d; asm("fma.rn.f32x2 %0,%1,%2,%3;" : "=l"(d) : "l"(a), "l"(b), "l"(c)); return d;
}

// ---- tensor-core helpers -------------------------------------------------
__device__ __forceinline__ void mma_bf16(float* c, const u32* a, const u32* b) {
    asm("mma.sync.aligned.m16n8k16.row.col.f32.bf16.bf16.f32 "
        "{%0,%1,%2,%3},{%4,%5,%6,%7},{%8,%9},{%0,%1,%2,%3};"
        : "+f"(c[0]), "+f"(c[1]), "+f"(c[2]), "+f"(c[3])
        : "r"(a[0]), "r"(a[1]), "r"(a[2]), "r"(a[3]), "r"(b[0]), "r"(b[1]));
}
__device__ __forceinline__ void ldmA(u32* a, u32 addr) {
    asm volatile("ldmatrix.sync.aligned.m8n8.x4.shared.b16 {%0,%1,%2,%3},[%4];"
        : "=r"(a[0]), "=r"(a[1]), "=r"(a[2]), "=r"(a[3]) : "r"(addr));
}
__device__ __forceinline__ void ldmAT(u32* a, u32 addr) {
    asm volatile("ldmatrix.sync.aligned.m8n8.x4.trans.shared.b16 {%0,%1,%2,%3},[%4];"
        : "=r"(a[0]), "=r"(a[1]), "=r"(a[2]), "=r"(a[3]) : "r"(addr));
}
__device__ __forceinline__ void ldmB(u32* b, u32 addr) {
    asm volatile("ldmatrix.sync.aligned.m8n8.x2.shared.b16 {%0,%1},[%2];"
        : "=r"(b[0]), "=r"(b[1]) : "r"(addr));
}
__device__ __forceinline__ void ldmBT(u32* b, u32 addr) {
    asm volatile("ldmatrix.sync.aligned.m8n8.x2.trans.shared.b16 {%0,%1},[%2];"
        : "=r"(b[0]), "=r"(b[1]) : "r"(addr));
}
__device__ __forceinline__ u32 smaddr(const void* p) {
    return (u32)__cvta_generic_to_shared(p);
}
__device__ __forceinline__ void bsplit2(float a, float b, u32& hi, u32& lo) {
    __nv_bfloat16 ha = __float2bfloat16(a), hb = __float2bfloat16(b);
    hi = (u32)__bfloat16_as_ushort(ha) | ((u32)__bfloat16_as_ushort(hb) << 16);
    float ra = a - __bfloat162float(ha), rb = b - __bfloat162float(hb);
    __nv_bfloat16 la = __float2bfloat16(ra), lb = __float2bfloat16(rb);
    lo = (u32)__bfloat16_as_ushort(la) | ((u32)__bfloat16_as_ushort(lb) << 16);
}

// ---------------- scratch ----------------
// y in mma A-fragment order: [selbc(512)][hblk(16)][kblk(32)][pair(2)][regm(2)][lane(32)] u32
__device__ u32   d_yFh[(size_t)512 * 65536];
__device__ u32   d_yFl[(size_t)512 * 65536];
__device__ float2 d_Fg [(size_t)BCD * Hh * WFD];
__device__ float2 d_Fx [(size_t)BCD * Hh * WFD];
__device__ float2 d_Gg [(size_t)BCD * Hh * WFD];
__device__ float2 d_Gx [(size_t)BCD * Hh * WFD];
__device__ float2 d_Sb [(size_t)BCD * WFD * WFD];
__device__ float2 d_Tb [(size_t)BCD * Hh * WFD];
__device__ float  d_rb [(size_t)BCD * HWD];
__device__ float  d_rsq[BCD * Hh];
__device__ float  d_vp [(size_t)BCD * Hh * 64];
__device__ float2 d_W256[256];
// mma-fragment-order DFT tables
__device__ u64 d_DwFrh[32768], d_DwFrl[32768], d_DwFih[32768], d_DwFil[32768];
__device__ u64 d_CwF1h[32768], d_CwF1l[32768], d_CwF2h[32768], d_CwF2l[32768];
// conv weight A-fragment tables
__device__ u64 d_WF[2][4][2048];

__device__ __forceinline__ void sp_bits(float x, u32& hb, u32& lb) {
    __nv_bfloat16 h = __float2bfloat16(x);
    hb = (u32)__bfloat16_as_ushort(h);
    lb = (u32)__bfloat16_as_ushort(__float2bfloat16(x - __bfloat162float(h)));
}

// ---------------- table builder ----------------
__global__ void build_tables_kernel() {
    int idx = blockIdx.x * blockDim.x + threadIdx.x;
    int stride = gridDim.x * blockDim.x;
    float rsW = rsqrtf(510.0f);

    for (int i = idx; i < 32768; i += stride) {
        int lane = i & 31, kblk = (i >> 5) & 31, nblk = i >> 10;
        int v = nblk * 8 + (lane >> 2);
        u32 prh[2], prl[2], pih[2], pil[2];
#pragma unroll
        for (int reg = 0; reg < 2; reg++) {
            prh[reg] = prl[reg] = pih[reg] = pil[reg] = 0;
#pragma unroll
            for (int e = 0; e < 2; e++) {
                int w = kblk * 16 + (lane & 3) * 2 + e + reg * 8;
                float re = 0.f, im = 0.f;
                if (w < Ww) {
                    int m = (w * v) % Ww;
                    float s, c; sincospif(2.0f * (float)m / (float)Ww, &s, &c);
                    re = c * rsW; im = -s * rsW;
                }
                u32 hb, lb;
                sp_bits(re, hb, lb);
                prh[reg] |= hb << (16 * e); prl[reg] |= lb << (16 * e);
                sp_bits(im, hb, lb);
                pih[reg] |= hb << (16 * e); pil[reg] |= lb << (16 * e);
            }
        }
        d_DwFrh[i] = (u64)prh[0] | ((u64)prh[1] << 32);
        d_DwFrl[i] = (u64)prl[0] | ((u64)prl[1] << 32);
        d_DwFih[i] = (u64)pih[0] | ((u64)pih[1] << 32);
        d_DwFil[i] = (u64)pil[0] | ((u64)pil[1] << 32);
    }
    for (int i = idx; i < 32768; i += stride) {
        int lane = i & 31, kblk = (i >> 5) & 15, nblk = i >> 9;
        int w = nblk * 8 + (lane >> 2);
        u32 p1h[2], p1l[2], p2h[2], p2l[2];
#pragma unroll
        for (int reg = 0; reg < 2; reg++) {
            p1h[reg] = p1l[reg] = p2h[reg] = p2l[reg] = 0;
#pragma unroll
            for (int e = 0; e < 2; e++) {
                int v = kblk * 16 + (lane & 3) * 2 + e + reg * 8;
                float b1 = 0.f, b2 = 0.f;
                if (w < Ww) {
                    int m = (v * w) % Ww;
                    float s, c; sincospif(2.0f * (float)m / (float)Ww, &s, &c);
                    float sv = (v == 0 || v == 255) ? 1.0f : 2.0f;
                    b1 = sv * c * rsW; b2 = -sv * s * rsW;
                }
                u32 hb, lb;
                sp_bits(b1, hb, lb);
                p1h[reg] |= hb << (16 * e); p1l[reg] |= lb << (16 * e);
                sp_bits(b2, hb, lb);
                p2h[reg] |= hb << (16 * e); p2l[reg] |= lb << (16 * e);
            }
        }
        d_CwF1h[i] = (u64)p1h[0] | ((u64)p1h[1] << 32);
        d_CwF1l[i] = (u64)p1l[0] | ((u64)p1l[1] << 32);
        d_CwF2h[i] = (u64)p2h[0] | ((u64)p2h[1] << 32);
        d_CwF2l[i] = (u64)p2l[0] | ((u64)p2l[1] << 32);
    }
    for (int j = idx; j < 256; j += stride) {
        float s, c; sincospif(2.0f * (float)j / 256.0f, &s, &c);
        d_W256[j] = make_float2(c, -s);
    }
}

// ---------------- zero w=510/511 fragment slots of y tables ----------------
__global__ void zero_pad_kernel() {
    int t = blockIdx.x * blockDim.x + threadIdx.x;   // 131072 total
    if (t >= 131072) return;
    int lane = (t & 7) * 4 + 3;
    int regm = (t >> 3) & 1;
    int hblk = (t >> 4) & 15;
    int sbc = t >> 8;
    size_t base = ((((size_t)sbc * 16 + hblk) * 32 + 31) * 4 + 2 + regm) * 32 + lane;
    d_yFh[base] = 0;
    d_yFl[base] = 0;
}

// ---------------- W pack ----------------
__global__ void pack_w_kernel(const float* __restrict__ wg, const float* __restrict__ wx) {
    int t = blockIdx.x * blockDim.x + threadIdx.x;
    if (t >= 4096) return;
    int wsel = t >> 11;
    int i = t & 2047;
    const float* W = wsel ? wx : wg;
    int lane = i & 31, kblk = (i >> 5) & 7, mblk = i >> 8;
    u32 qh[4], ql[4];
#pragma unroll
    for (int reg = 0; reg < 4; reg++) {
        int row = mblk * 16 + (lane >> 2) + 8 * (reg & 1);
        u32 hi = 0, lo = 0;
#pragma unroll
        for (int e = 0; e < 2; e++) {
            int k = kblk * 16 + (lane & 3) * 2 + e + 8 * (reg >> 1);
            float v = W[row * 128 + k];
            u32 hb, lb; sp_bits(v, hb, lb);
            hi |= hb << (16 * e); lo |= lb << (16 * e);
        }
        qh[reg] = hi; ql[reg] = lo;
    }
    d_WF[wsel][0][i] = (u64)qh[0] | ((u64)qh[1] << 32);
    d_WF[wsel][1][i] = (u64)ql[0] | ((u64)ql[1] << 32);
    d_WF[wsel][2][i] = (u64)qh[2] | ((u64)qh[3] << 32);
    d_WF[wsel][3][i] = (u64)ql[2] | ((u64)ql[3] << 32);
}

__device__ __forceinline__ float sigm(float v) { return 1.f / (1.f + expf(-v)); }

#define PITS 72
#define SSZ  (32 * PITS)

// -------- 1x1 conv — merged g/x; epilogue stores y in A-fragment order ------
__global__ void __launch_bounds__(256, 2) conv_tc(
    const float* __restrict__ g, const float* __restrict__ x,
    const float* __restrict__ bg, const float* __restrict__ bx)
{
    __shared__ __nv_bfloat16 sXh[2][SSZ], sXl[2][SSZ];
    int z = blockIdx.z;
    int b = z & 1, wsel = z >> 1;
    const float* Xb = (wsel ? x : g) + (size_t)b * Cc * HWD;
    const float* bias = wsel ? bx : bg;
    int base_bc = wsel * 256 + b * 128;
    int n0 = blockIdx.x * 64, m0 = blockIdx.y * 64;
    int t = threadIdx.x, lane = t & 31, wid = t >> 5;
    int wm = (wid >> 2) * 32, wn = (wid & 3) * 16;
    int g4 = lane >> 2, tc4 = lane & 3;

    float acc[2][2][4];
#pragma unroll
    for (int i = 0; i < 2; i++)
#pragma unroll
        for (int j = 0; j < 2; j++)
#pragma unroll
            for (int q = 0; q < 4; q++) acc[i][j][q] = 0.f;

    int kB = (lane & 7) + ((lane >> 3) & 1) * 8;
    int scB = t & 31, srB = t >> 5;
    int mblk_base = (m0 + wm) >> 4;

    float2 xv[4];
#define CONV_LOAD(K0) { \
    _Pragma("unroll") \
    for (int i = 0; i < 4; i++) \
        xv[i] = *(const float2*)&Xb[(size_t)((K0) + srB + i * 8) * HWD + n0 + 2 * scB]; }
#define CONV_STORE(BF) { \
    _Pragma("unroll") \
    for (int i = 0; i < 4; i++) { \
        u32 hi, lo; bsplit2(xv[i].x, xv[i].y, hi, lo); \
        int so = (srB + i * 8) * PITS + 2 * scB; \
        *(u32*)&sXh[BF][so] = hi; *(u32*)&sXl[BF][so] = lo; \
    } }

    CONV_LOAD(0)
    CONV_STORE(0)
    __syncthreads();
    for (int it = 0; it < 4; it++) {
        int buf = it & 1;
        if (it < 3) CONV_LOAD((it + 1) * 32)
        u32 aXh = smaddr(sXh[buf]), aXl = smaddr(sXl[buf]);
#pragma unroll
        for (int ks = 0; ks < 2; ks++) {
            int kb = ks * 16;
            int kblk = it * 2 + ks;
            u32 ah[2][4], al[2][4];
#pragma unroll
            for (int tm = 0; tm < 2; tm++) {
                size_t bi = ((size_t)((mblk_base + tm) * 8 + kblk) << 5) + lane;
                u64 v;
                v = d_WF[wsel][0][bi]; ah[tm][0] = (u32)v; ah[tm][1] = (u32)(v >> 32);
                v = d_WF[wsel][2][bi]; ah[tm][2] = (u32)v; ah[tm][3] = (u32)(v >> 32);
                v = d_WF[wsel][1][bi]; al[tm][0] = (u32)v; al[tm][1] = (u32)(v >> 32);
                v = d_WF[wsel][3][bi]; al[tm][2] = (u32)v; al[tm][3] = (u32)(v >> 32);
            }
            u32 bh[2][2], bl[2][2];
#pragma unroll
            for (int tn = 0; tn < 2; tn++) {
                u32 off = ((kb + kB) * PITS + wn + 8 * tn) * 2;
                ldmBT(bh[tn], aXh + off);
                ldmBT(bl[tn], aXl + off);
            }
#pragma unroll
            for (int tm = 0; tm < 2; tm++)
#pragma unroll
                for (int tn = 0; tn < 2; tn++) {
                    mma_bf16(acc[tm][tn], ah[tm], bh[tn]);
                    mma_bf16(acc[tm][tn], ah[tm], bl[tn]);
                    mma_bf16(acc[tm][tn], al[tm], bh[tn]);
                }
        }
        if (it < 3) CONV_STORE(buf ^ 1)
        __syncthreads();
    }
#undef CONV_LOAD
#undef CONV_STORE
#pragma unroll
    for (int tm = 0; tm < 2; tm++)
#pragma unroll
        for (int tn = 0; tn < 2; tn++) {
            int cout = m0 + wm + 16 * tm + g4;
            int col = n0 + wn + 8 * tn + 2 * tc4;
            u32 h = (u32)col / 510u;
            u32 w = (u32)col - h * 510u;
            size_t tb = ((((size_t)(base_bc + cout) * 16 + (h >> 4)) * 32 + (w >> 4)) * 4
                         + ((w >> 3) & 1) * 2 + ((h >> 3) & 1)) * 32
                        + (h & 7) * 4 + ((w & 7) >> 1);
            float bv0 = bias[cout], bv1 = bias[cout + 8];
            u32 hi, lo;
            bsplit2(acc[tm][tn][0] + bv0, acc[tm][tn][1] + bv0, hi, lo);
            d_yFh[tb] = hi; d_yFl[tb] = lo;
            size_t tb2 = tb + (size_t)8 * 65536;   // cout+8 -> bc+8
            bsplit2(acc[tm][tn][2] + bv1, acc[tm][tn][3] + bv1, hi, lo);
            d_yFh[tb2] = hi; d_yFl[tb2] = lo;
        }
}

// ------- rfft along W — fragment-direct A (pre-permuted) and B; no smem -------
__global__ void __launch_bounds__(256) rfftw_tc(
    float2* __restrict__ Fg, float2* __restrict__ Fx)
{
    int z = blockIdx.z;                 // = sel*256 + bc, matches table index
    float2* Cp = ((z >> 8) ? Fx : Fg) + (size_t)(z & 255) * Hh * WFD;
    int n0 = blockIdx.x * 64, m0 = blockIdx.y * 64;
    int t = threadIdx.x, lane = t & 31, wid = t >> 5;
    int wm = (wid >> 2) * 32, wn = (wid & 3) * 16;
    int g = lane >> 2, tc = lane & 3;

    float cre[2][2][4], cim[2][2][4];
#pragma unroll
    for (int i = 0; i < 2; i++)
#pragma unroll
        for (int j = 0; j < 2; j++)
#pragma unroll
            for (int q = 0; q < 4; q++) { cre[i][j][q] = 0.f; cim[i][j][q] = 0.f; }

    int nblk0 = (n0 + wn) >> 3;
    int hblk0 = (m0 + wm) >> 4;

    for (int kblk = 0; kblk < 32; kblk++) {
        u32 ah[2][4], al[2][4];
#pragma unroll
        for (int tm = 0; tm < 2; tm++) {
            size_t base = (((size_t)z * 16 + hblk0 + tm) * 32 + kblk) * 128 + lane;
            ah[tm][0] = d_yFh[base];
            ah[tm][1] = d_yFh[base + 32];
            ah[tm][2] = d_yFh[base + 64];
            ah[tm][3] = d_yFh[base + 96];
            al[tm][0] = d_yFl[base];
            al[tm][1] = d_yFl[base + 32];
            al[tm][2] = d_yFl[base + 64];
            al[tm][3] = d_yFl[base + 96];
        }
        u32 brh[2][2], brl[2][2], bih[2][2], bil[2][2];
#pragma unroll
        for (int tn = 0; tn < 2; tn++) {
            size_t bi = ((size_t)((nblk0 + tn) * 32 + kblk) << 5) + lane;
            u64 v;
            v = d_DwFrh[bi]; brh[tn][0] = (u32)v; brh[tn][1] = (u32)(v >> 32);
            v = d_DwFrl[bi]; brl[tn][0] = (u32)v; brl[tn][1] = (u32)(v >> 32);
            v = d_DwFih[bi]; bih[tn][0] = (u32)v; bih[tn][1] = (u32)(v >> 32);
            v = d_DwFil[bi]; bil[tn][0] = (u32)v; bil[tn][1] = (u32)(v >> 32);
        }
#pragma unroll
        for (int tm = 0; tm < 2; tm++)
#pragma unroll
            for (int tn = 0; tn < 2; tn++) {
                mma_bf16(cre[tm][tn], ah[tm], brh[tn]);
                mma_bf16(cre[tm][tn], ah[tm], brl[tn]);
                mma_bf16(cre[tm][tn], al[tm], brh[tn]);
                mma_bf16(cim[tm][tn], ah[tm], bih[tn]);
                mma_bf16(cim[tm][tn], ah[tm], bil[tn]);
                mma_bf16(cim[tm][tn], al[tm], bih[tn]);
            }
    }
#pragma unroll
    for (int tm = 0; tm < 2; tm++)
#pragma unroll
        for (int tn = 0; tn < 2; tn++) {
            int r0 = m0 + wm + 16 * tm + g;
            int col = n0 + wn + 8 * tn + 2 * tc;
            float4 v0 = make_float4(cre[tm][tn][0], cim[tm][tn][0], cre[tm][tn][1], cim[tm][tn][1]);
            *(float4*)&Cp[(size_t)r0 * WFD + col] = v0;
            float4 v1 = make_float4(cre[tm][tn][2], cim[tm][tn][2], cre[tm][tn][3], cim[tm][tn][3]);
            *(float4*)&Cp[(size_t)(r0 + 8) * WFD + col] = v1;
        }
}

// ------- irfft along W + residual — HMMA, smem-staged (R14 form) ----
#define PIT  40
#define ASZ  (64 * PIT)
__global__ void __launch_bounds__(256, 2) irfft_add_tc(
    const float2* __restrict__ T, const float* __restrict__ x, float* __restrict__ r)
{
    __shared__ __nv_bfloat16 sArh[2][ASZ], sArl[2][ASZ], sAih[2][ASZ], sAil[2][ASZ];
    int bc = blockIdx.z;
    const float2* Ap = T + (size_t)bc * 65536;
    int n0 = blockIdx.x * 64, m0 = blockIdx.y * 64;
    int t = threadIdx.x, lane = t & 31, wid = t >> 5;
    int wm = (wid >> 2) * 32, wn = (wid & 3) * 16;
    int g = lane >> 2, tc = lane & 3;

    float acc[2][2][4];
#pragma unroll
    for (int i = 0; i < 2; i++)
#pragma unroll
        for (int j = 0; j < 2; j++)
#pragma unroll
            for (int q = 0; q < 4; q++) acc[i][j][q] = 0.f;

    int lrA = lane & 15, lkA = (lane >> 4) * 8;
    int sc = t & 15, sr = t >> 4;
    int nblk0 = (n0 + wn) >> 3;

    float4 va[4];
#define IRF_LOAD(K0) { \
    _Pragma("unroll") \
    for (int i = 0; i < 4; i++) { \
        int rr = sr + i * 16; \
        va[i] = *(const float4*)&Ap[(size_t)(m0 + rr) * 256 + (K0) + 2 * sc]; \
    } }
#define IRF_STORE(BF) { \
    _Pragma("unroll") \
    for (int i = 0; i < 4; i++) { \
        int so = (sr + i * 16) * PIT + 2 * sc; \
        u32 hi, lo; \
        bsplit2(va[i].x, va[i].z, hi, lo); \
        *(u32*)&sArh[BF][so] = hi; *(u32*)&sArl[BF][so] = lo; \
        bsplit2(va[i].y, va[i].w, hi, lo); \
        *(u32*)&sAih[BF][so] = hi; *(u32*)&sAil[BF][so] = lo; \
    } }

    IRF_LOAD(0)
    IRF_STORE(0)
    __syncthreads();
    for (int it = 0; it < 8; it++) {
        int buf = it & 1;
        if (it < 7) IRF_LOAD((it + 1) * 32)
        u32 aArh = smaddr(sArh[buf]), aArl = smaddr(sArl[buf]);
        u32 aAih = smaddr(sAih[buf]), aAil = smaddr(sAil[buf]);
#pragma unroll
        for (int ks = 0; ks < 2; ks++) {
            int kb = ks * 16;
            int kblk = it * 2 + ks;
            u32 arh[2][4], arl[2][4], aih[2][4], ail[2][4];
#pragma unroll
            for (int tm = 0; tm < 2; tm++) {
                u32 off = ((wm + 16 * tm + lrA) * PIT + kb + lkA) * 2;
                ldmA(arh[tm], aArh + off);
                ldmA(arl[tm], aArl + off);
                ldmA(aih[tm], aAih + off);
                ldmA(ail[tm], aAil + off);
            }
            u32 b1h[2][2], b1l[2][2], b2h[2][2], b2l[2][2];
#pragma unroll
            for (int tn = 0; tn < 2; tn++) {
                size_t bi = ((size_t)((nblk0 + tn) * 16 + kblk) << 5) + lane;
                u64 v;
                v = d_CwF1h[bi]; b1h[tn][0] = (u32)v; b1h[tn][1] = (u32)(v >> 32);
                v = d_CwF1l[bi]; b1l[tn][0] = (u32)v; b1l[tn][1] = (u32)(v >> 32);
                v = d_CwF2h[bi]; b2h[tn][0] = (u32)v; b2h[tn][1] = (u32)(v >> 32);
                v = d_CwF2l[bi]; b2l[tn][0] = (u32)v; b2l[tn][1] = (u32)(v >> 32);
            }
#pragma unroll
            for (int tm = 0; tm < 2; tm++)
#pragma unroll
                for (int tn = 0; tn < 2; tn++) {
                    mma_bf16(acc[tm][tn], arh[tm], b1h[tn]);
                    mma_bf16(acc[tm][tn], arh[tm], b1l[tn]);
                    mma_bf16(acc[tm][tn], arl[tm], b1h[tn]);
                    mma_bf16(acc[tm][tn], aih[tm], b2h[tn]);
                    mma_bf16(acc[tm][tn], aih[tm], b2l[tn]);
                    mma_bf16(acc[tm][tn], ail[tm], b2h[tn]);
                }
        }
        if (it < 7) IRF_STORE(buf ^ 1)
        __syncthreads();
    }
#undef IRF_LOAD
#undef IRF_STORE
#pragma unroll
    for (int tm = 0; tm < 2; tm++)
#pragma unroll
        for (int tn = 0; tn < 2; tn++) {
            int col = n0 + wn + 8 * tn + 2 * tc;
            if (col < Ww) {
                int r0 = m0 + wm + 16 * tm + g;
                size_t i0 = (size_t)bc * HWD + (size_t)r0 * Ww + col;
                size_t i1 = i0 + (size_t)8 * Ww;
                float2 xv = *(const float2*)&x[i0];
                *(float2*)&r[i0] = make_float2(acc[tm][tn][0] + xv.x, acc[tm][tn][1] + xv.y);
                xv = *(const float2*)&x[i1];
                *(float2*)&r[i1] = make_float2(acc[tm][tn][2] + xv.x, acc[tm][tn][3] + xv.y);
            }
        }
}

// ---------------- forward ffth (merged g/x) + fused variance partials ------
__global__ void __launch_bounds__(256) ffth_fwd(
    const float2* __restrict__ Fg, const float2* __restrict__ Fx,
    float2* __restrict__ Gg, float2* __restrict__ Gx,
    const float2* __restrict__ fg, const float2* __restrict__ fx,
    float* __restrict__ vp)
{
    __shared__ float2 Xs[256][17];
    __shared__ float2 Ws[256];
    int yz = blockIdx.y;
    int sel = yz >> 8, bc = yz & 255;
    const float2* inp = (sel ? Fx : Fg) + (size_t)bc * 65536;
    float2* outp = (sel ? Gx : Gg) + (size_t)bc * 65536;
    const float2* filt = sel ? fx : fg;
    int v0 = blockIdx.x * 16;
    int tx = threadIdx.x;
    int ty = threadIdx.y;
    int t = ty * 16 + tx;

    {
        float2 w = d_W256[t];
        Ws[t] = w;
    }
#pragma unroll
    for (int i = 0; i < 16; i++) {
        int h = i * 16 + ty;
        Xs[h][tx] = inp[(size_t)h * 256 + v0 + tx];
    }
    __syncthreads();

    float2 rr[16];
    {
        u64 tw[16];
#pragma unroll
        for (int n1 = 0; n1 < 16; n1++) {
            float2 w = Ws[(n1 * ty * 16) & 255];
            tw[n1] = pk2(w.x, w.y);
        }
#pragma unroll
        for (int n2 = 0; n2 < 16; n2++) {
            u64 accA = 0ull, accB = 0ull;
#pragma unroll
            for (int n1 = 0; n1 < 16; n1++) {
                float2 xv = Xs[16 * n1 + n2][tx];
                u64 xp = pk2(xv.x, xv.y);
                u64 xq = pk2(xv.y, xv.x);
                accA = ffma2(xp, tw[n1], accA);
                accB = ffma2(xq, tw[n1], accB);
            }
            float2 a = up2(accA), b = up2(accB);
            float ar = a.x - a.y, ai = b.x + b.y;
            float2 tm = Ws[(n2 * ty) & 255];
            rr[n2] = make_float2(ar * tm.x - ai * tm.y, ar * tm.y + ai * tm.x);
        }
    }
    __syncthreads();
#pragma unroll
    for (int n2 = 0; n2 < 16; n2++)
        Xs[ty * 16 + n2][tx] = rr[n2];
    __syncthreads();

    {
        u64 tw[16];
#pragma unroll
        for (int n2 = 0; n2 < 16; n2++) {
            float2 w = Ws[(n2 * ty * 16) & 255];
            tw[n2] = pk2(w.x, w.y);
        }
        int c = bc & (Cc - 1);
#pragma unroll
        for (int k1 = 0; k1 < 16; k1++) {
            u64 accA = 0ull, accB = 0ull;
#pragma unroll
            for (int n2 = 0; n2 < 16; n2++) {
                float2 xv = Xs[k1 * 16 + n2][tx];
                u64 xp = pk2(xv.x, xv.y);
                u64 xq = pk2(xv.y, xv.x);
                accA = ffma2(xp, tw[n2], accA);
                accB = ffma2(xq, tw[n2], accB);
            }
            float2 a = up2(accA), b = up2(accB);
            int u = k1 + 16 * ty;
            float2 v = make_float2((a.x - a.y) * 0.0625f, (b.x + b.y) * 0.0625f);
            float2 wc = filt[((size_t)c * Hh + u) * WFD + v0 + tx];
            v = make_float2(v.x * wc.x - v.y * wc.y, v.x * wc.y + v.y * wc.x);
            outp[(size_t)u * 256 + v0 + tx] = v;
            if (sel == 0) {
                float sre = v.x, sim = v.y, ssq = v.x * v.x + v.y * v.y;
#pragma unroll
                for (int msk = 8; msk >= 1; msk >>= 1) {
                    sre += __shfl_xor_sync(0xFFFFFFFFu, sre, msk);
                    sim += __shfl_xor_sync(0xFFFFFFFFu, sim, msk);
                    ssq += __shfl_xor_sync(0xFFFFFFFFu, ssq, msk);
                }
                if (tx == 0) {
                    size_t idx = (((size_t)bc * 256 + u) * 16 + blockIdx.x) * 4;
                    *(float4*)&vp[idx] = make_float4(sre, sim, ssq, 0.f);
                }
            }
        }
    }
}

// ------- variance finalize -------
__global__ void var_fin(const float* __restrict__ vp, float* __restrict__ rsq)
{
    int row = blockIdx.x * 256 + threadIdx.x;
    const float4* p = (const float4*)(vp + (size_t)row * 64);
    float sre = 0.f, sim = 0.f, ssq = 0.f;
#pragma unroll
    for (int i = 0; i < 16; i++) {
        float4 v = p[i];
        sre += v.x; sim += v.y; ssq += v.z;
    }
    float mr = sre * (1.f / 256.f), mi = sim * (1.f / 256.f);
    float var = ssq * (1.f / 256.f) - mr * mr - mi * mi;
    rsq[row] = 1.f / sqrtf(6.283185307179586f * var);
}

// ---------------- inverse ffth ----------------
__global__ void __launch_bounds__(256) ffth_inv(
    const float2* __restrict__ in, float2* __restrict__ out)
{
    __shared__ float2 Xs[256][17];
    __shared__ float2 Ws[256];
    int bc = blockIdx.y;
    int v0 = blockIdx.x * 16;
    int tx = threadIdx.x;
    int ty = threadIdx.y;
    int t = ty * 16 + tx;
    const float2* inp = in + (size_t)bc * 65536 + v0;
    float2* outp = out + (size_t)bc * 65536 + v0;

    {
        float2 w = d_W256[t];
        w.y = -w.y;
        Ws[t] = w;
    }
#pragma unroll
    for (int i = 0; i < 16; i++) {
        int h = i * 16 + ty;
        Xs[h][tx] = inp[(size_t)h * 256 + tx];
    }
    __syncthreads();

    float2 rr[16];
    {
        u64 tw[16];
#pragma unroll
        for (int n1 = 0; n1 < 16; n1++) {
            float2 w = Ws[(n1 * ty * 16) & 255];
            tw[n1] = pk2(w.x, w.y);
        }
#pragma unroll
        for (int n2 = 0; n2 < 16; n2++) {
            u64 accA = 0ull, accB = 0ull;
#pragma unroll
            for (int n1 = 0; n1 < 16; n1++) {
                float2 xv = Xs[16 * n1 + n2][tx];
                u64 xp = pk2(xv.x, xv.y);
                u64 xq = pk2(xv.y, xv.x);
                accA = ffma2(xp, tw[n1], accA);
                accB = ffma2(xq, tw[n1], accB);
            }
            float2 a = up2(accA), b = up2(accB);
            float ar = a.x - a.y, ai = b.x + b.y;
            float2 tm = Ws[(n2 * ty) & 255];
            rr[n2] = make_float2(ar * tm.x - ai * tm.y, ar * tm.y + ai * tm.x);
        }
    }
    __syncthreads();
#pragma unroll
    for (int n2 = 0; n2 < 16; n2++)
        Xs[ty * 16 + n2][tx] = rr[n2];
    __syncthreads();

    {
        u64 tw[16];
#pragma unroll
        for (int n2 = 0; n2 < 16; n2++) {
            float2 w = Ws[(n2 * ty * 16) & 255];
            tw[n2] = pk2(w.x, w.y);
        }
#pragma unroll
        for (int k1 = 0; k1 < 16; k1++) {
            u64 accA = 0ull, accB = 0ull;
#pragma unroll
            for (int n2 = 0; n2 < 16; n2++) {
                float2 xv = Xs[k1 * 16 + n2][tx];
                u64 xp = pk2(xv.x, xv.y);
                u64 xq = pk2(xv.y, xv.x);
                accA = ffma2(xp, tw[n2], accA);
                accB = ffma2(xq, tw[n2], accB);
            }
            float2 a = up2(accA), b = up2(accB);
            int u = k1 + 16 * ty;
            float2 v = make_float2((a.x - a.y) * 0.0625f, (b.x + b.y) * 0.0625f);
            outp[(size_t)u * 256 + tx] = v;
        }
    }
}

// ------- scores — HMMA complex, double-buffered (dynamic smem) -------
__global__ void __launch_bounds__(256) scores_tc(
    const float2* __restrict__ Gb, const float2* __restrict__ Xb,
    const float* __restrict__ rsq, float2* __restrict__ Sb)
{
    extern __shared__ __nv_bfloat16 dynS[];
    __nv_bfloat16* sGrh = dynS;
    __nv_bfloat16* sGrl = sGrh + 2 * SSZ;
    __nv_bfloat16* sGih = sGrl + 2 * SSZ;
    __nv_bfloat16* sGil = sGih + 2 * SSZ;
    __nv_bfloat16* sXrh = sGil + 2 * SSZ;
    __nv_bfloat16* sXrl = sXrh + 2 * SSZ;
    __nv_bfloat16* sXih = sXrl + 2 * SSZ;
    __nv_bfloat16* sXil = sXih + 2 * SSZ;
    int bc = blockIdx.z;
    const float2* Ap = Gb + (size_t)bc * 65536;
    const float2* Bp = Xb + (size_t)bc * 65536;
    float2* Cp = Sb + (size_t)bc * 65536;
    int n0 = blockIdx.x * 64, m0 = blockIdx.y * 64;
    int t = threadIdx.x, lane = t & 31, wid = t >> 5;
    int wm = (wid >> 2) * 32, wn = (wid & 3) * 16;
    int g = lane >> 2, tc4 = lane & 3;

    float are[2][2][4], aim[2][2][4];
#pragma unroll
    for (int i = 0; i < 2; i++)
#pragma unroll
        for (int j = 0; j < 2; j++)
#pragma unroll
            for (int q = 0; q < 4; q++) { are[i][j][q] = 0.f; aim[i][j][q] = 0.f; }

    int kA = (lane & 7) + ((lane >> 4) & 1) * 8;
    int mA = ((lane >> 3) & 1) * 8;
    int kB = (lane & 7) + ((lane >> 3) & 1) * 8;
    int sc = t & 31, sr = t >> 5;

    float4 vA[4], vB[4];
#define SCR_LOAD(K0) { \
    _Pragma("unroll") \
    for (int i = 0; i < 4; i++) { \
        int k = sr + i * 8; \
        vA[i] = *(const float4*)&Ap[(size_t)((K0) + k) * 256 + m0 + 2 * sc]; \
        vB[i] = *(const float4*)&Bp[(size_t)((K0) + k) * 256 + n0 + 2 * sc]; \
    } }
#define SCR_STORE(BF) { \
    _Pragma("unroll") \
    for (int i = 0; i < 4; i++) { \
        int so = (BF) * SSZ + (sr + i * 8) * PITS + 2 * sc; \
        u32 hi, lo; \
        bsplit2(vA[i].x, vA[i].z, hi, lo); *(u32*)&sGrh[so] = hi; *(u32*)&sGrl[so] = lo; \
        bsplit2(vA[i].y, vA[i].w, hi, lo); *(u32*)&sGih[so] = hi; *(u32*)&sGil[so] = lo; \
        bsplit2(vB[i].x, vB[i].z, hi, lo); *(u32*)&sXrh[so] = hi; *(u32*)&sXrl[so] = lo; \
        bsplit2(vB[i].y, vB[i].w, hi, lo); *(u32*)&sXih[so] = hi; *(u32*)&sXil[so] = lo; \
    } }

    SCR_LOAD(0)
    SCR_STORE(0)
    __syncthreads();
    for (int it = 0; it < 8; it++) {
        int buf = it & 1;
        if (it < 7) SCR_LOAD((it + 1) * 32)
        u32 aGrh = smaddr(sGrh + buf * SSZ), aGrl = smaddr(sGrl + buf * SSZ);
        u32 aGih = smaddr(sGih + buf * SSZ), aGil = smaddr(sGil + buf * SSZ);
        u32 aXrh = smaddr(sXrh + buf * SSZ), aXrl = smaddr(sXrl + buf * SSZ);
        u32 aXih = smaddr(sXih + buf * SSZ), aXil = smaddr(sXil + buf * SSZ);
#pragma unroll
        for (int ks = 0; ks < 2; ks++) {
            int kb = ks * 16;
            u32 grh[2][4], grl[2][4], gih[2][4], gil[2][4];
#pragma unroll
            for (int tm = 0; tm < 2; tm++) {
                u32 off = ((kb + kA) * PITS + wm + 16 * tm + mA) * 2;
                ldmAT(grh[tm], aGrh + off);
                ldmAT(grl[tm], aGrl + off);
                ldmAT(gih[tm], aGih + off);
                ldmAT(gil[tm], aGil + off);
            }
            u32 xrh[2][2], xrl[2][2], xih[2][2], xil[2][2];
#pragma unroll
            for (int tn = 0; tn < 2; tn++) {
                u32 off = ((kb + kB) * PITS + wn + 8 * tn) * 2;
                ldmBT(xrh[tn], aXrh + off);
                ldmBT(xrl[tn], aXrl + off);
                ldmBT(xih[tn], aXih + off);
                ldmBT(xil[tn], aXil + off);
            }
#pragma unroll
            for (int tm = 0; tm < 2; tm++) {
                u32 nih[4], nil_[4];
#pragma unroll
                for (int q = 0; q < 4; q++) {
                    nih[q]  = gih[tm][q] ^ 0x80008000u;
                    nil_[q] = gil[tm][q] ^ 0x80008000u;
                }
#pragma unroll
                for (int tn = 0; tn < 2; tn++) {
                    mma_bf16(are[tm][tn], grh[tm], xrh[tn]);
                    mma_bf16(are[tm][tn], grh[tm], xrl[tn]);
                    mma_bf16(are[tm][tn], grl[tm], xrh[tn]);
                    mma_bf16(are[tm][tn], nih,     xih[tn]);
                    mma_bf16(are[tm][tn], nih,     xil[tn]);
                    mma_bf16(are[tm][tn], nil_,    xih[tn]);
                    mma_bf16(aim[tm][tn], grh[tm], xih[tn]);
                    mma_bf16(aim[tm][tn], grh[tm], xil[tn]);
                    mma_bf16(aim[tm][tn], grl[tm], xih[tn]);
                    mma_bf16(aim[tm][tn], gih[tm], xrh[tn]);
                    mma_bf16(aim[tm][tn], gih[tm], xrl[tn]);
                    mma_bf16(aim[tm][tn], gil[tm], xrh[tn]);
                }
            }
        }
        if (it < 7) SCR_STORE(buf ^ 1)
        __syncthreads();
    }
#undef SCR_LOAD
#undef SCR_STORE
#pragma unroll
    for (int tm = 0; tm < 2; tm++)
#pragma unroll
        for (int tn = 0; tn < 2; tn++) {
            int r0 = m0 + wm + 16 * tm + g;
            int col = n0 + wn + 8 * tn + 2 * tc4;
            float s0 = rsq[bc * Hh + r0], s1 = rsq[bc * Hh + r0 + 8];
            float4 o0 = make_float4(
                sigm(are[tm][tn][0] * s0), sigm(aim[tm][tn][0] * s0),
                sigm(are[tm][tn][1] * s0), sigm(aim[tm][tn][1] * s0));
            *(float4*)&Cp[(size_t)r0 * 256 + col] = o0;
            float4 o1 = make_float4(
                sigm(are[tm][tn][2] * s1), sigm(aim[tm][tn][2] * s1),
                sigm(are[tm][tn][3] * s1), sigm(aim[tm][tn][3] * s1));
            *(float4*)&Cp[(size_t)(r0 + 8) * 256 + col] = o1;
        }
}

// ------- channel LayerNorm — float4 smem-tiled -------
#define LN_SMEM ((128 * 32 + 2 * 8 * 32 + 64) * 16)
__global__ void __launch_bounds__(256) ln_kernel(
    const float* __restrict__ r, const float* __restrict__ gamma,
    const float* __restrict__ beta, float* __restrict__ out)
{
    extern __shared__ float4 lns[];
    float4* tile = lns;
    float4* ps   = tile + 128 * 32;
    float4* qs   = ps + 8 * 32;
    float4* muv  = qs + 8 * 32;
    float4* invv = muv + 32;
    int blk = blockIdx.x;
    int b = blk / 1020;
    int w0 = (blk - b * 1020) * 128;
    int t = threadIdx.x;
    int w4 = t & 31, cq = t >> 5;

    float4 s = make_float4(0.f, 0.f, 0.f, 0.f);
    float4 q = make_float4(0.f, 0.f, 0.f, 0.f);
#pragma unroll
    for (int c0 = 0; c0 < 128; c0 += 8) {
        int c = c0 + cq;
        float4 v = *(const float4*)&r[(size_t)(b * Cc + c) * HWD + w0 + w4 * 4];
        tile[c * 32 + w4] = v;
        s.x += v.x; s.y += v.y; s.z += v.z; s.w += v.w;
        q.x += v.x * v.x; q.y += v.y * v.y; q.z += v.z * v.z; q.w += v.w * v.w;
    }
    ps[cq * 32 + w4] = s;
    qs[cq * 32 + w4] = q;
    __syncthreads();
    if (t < 32) {
        float4 S = make_float4(0.f, 0.f, 0.f, 0.f);
        float4 Q = make_float4(0.f, 0.f, 0.f, 0.f);
#pragma unroll
        for (int i = 0; i < 8; i++) {
            float4 a = ps[i * 32 + t];
            S.x += a.x; S.y += a.y; S.z += a.z; S.w += a.w;
            a = qs[i * 32 + t];
            Q.x += a.x; Q.y += a.y; Q.z += a.z; Q.w += a.w;
        }
        float4 m = make_float4(S.x * (1.f / 128.f), S.y * (1.f / 128.f),
                               S.z * (1.f / 128.f), S.w * (1.f / 128.f));
        float4 iv;
        iv.x = rsqrtf(Q.x * (1.f / 128.f) - m.x * m.x + 1e-6f);
        iv.y = rsqrtf(Q.y * (1.f / 128.f) - m.y * m.y + 1e-6f);
        iv.z = rsqrtf(Q.z * (1.f / 128.f) - m.z * m.z + 1e-6f);
        iv.w = rsqrtf(Q.w * (1.f / 128.f) - m.w * m.w + 1e-6f);
        muv[t] = m;
        invv[t] = iv;
    }
    __syncthreads();
    float4 m = muv[w4], iv = invv[w4];
#pragma unroll
    for (int c0 = 0; c0 < 128; c0 += 8) {
        int c = c0 + cq;
        float4 v = tile[c * 32 + w4];
        float gm = gamma[c], bt = beta[c];
        float4 o;
        o.x = gm * (v.x - m.x) * iv.x + bt;
        o.y = gm * (v.y - m.y) * iv.y + bt;
        o.z = gm * (v.z - m.z) * iv.z + bt;
        o.w = gm * (v.w - m.w) * iv.w + bt;
        *(float4*)&out[(size_t)(b * Cc + c) * HWD + w0 + w4 * 4] = o;
    }
}

// ---------------- launch ----------------
extern "C" void kernel_launch(void* const* d_in, const int* in_sizes, int n_in,
                              void* d_out, int out_size)
{
    (void)in_sizes; (void)n_in; (void)out_size;
    const float*  g     = (const float*)d_in[0];
    const float*  x     = (const float*)d_in[1];
    const float*  wg    = (const float*)d_in[2];
    const float*  bg    = (const float*)d_in[3];
    const float*  wx    = (const float*)d_in[4];
    const float*  bx    = (const float*)d_in[5];
    const float2* fg    = (const float2*)d_in[6];
    const float2* fx    = (const float2*)d_in[7];
    const float*  gamma = (const float*)d_in[8];
    const float*  beta  = (const float*)d_in[9];
    float* out = (float*)d_out;

    float *rb, *rsq, *vp;
    float2 *Fg, *Fx, *Gg, *Gx, *S, *T;
    cudaGetSymbolAddress((void**)&Fg,  d_Fg);
    cudaGetSymbolAddress((void**)&Fx,  d_Fx);
    cudaGetSymbolAddress((void**)&Gg,  d_Gg);
    cudaGetSymbolAddress((void**)&Gx,  d_Gx);
    cudaGetSymbolAddress((void**)&S,   d_Sb);
    cudaGetSymbolAddress((void**)&T,   d_Tb);
    cudaGetSymbolAddress((void**)&rb,  d_rb);
    cudaGetSymbolAddress((void**)&rsq, d_rsq);
    cudaGetSymbolAddress((void**)&vp,  d_vp);

    static int attr_done = 0;
    if (!attr_done) {
        cudaFuncSetAttribute(scores_tc, cudaFuncAttributeMaxDynamicSharedMemorySize,
                             16 * SSZ * 2);
        cudaFuncSetAttribute(ln_kernel, cudaFuncAttributeMaxDynamicSharedMemorySize,
                             LN_SMEM);
        attr_done = 1;
    }

    dim3 blk(16, 16);

    build_tables_kernel<<<512, 256>>>();
    pack_w_kernel<<<16, 256>>>(wg, wx);
    zero_pad_kernel<<<512, 256>>>();

    conv_tc<<<dim3(HWD / 64, 2, 2 * Bb), 256>>>(g, x, bg, bx);

    rfftw_tc<<<dim3(4, 4, 2 * BCD), 256>>>(Fg, Fx);

    ffth_fwd<<<dim3(16, 2 * BCD), blk>>>(Fg, Fx, Gg, Gx, fg, fx, vp);

    var_fin<<<BCD * Hh / 256, 256>>>(vp, rsq);

    scores_tc<<<dim3(4, 4, BCD), 256, 16 * SSZ * 2>>>(Gg, Gx, rsq, S);

    ffth_inv<<<dim3(16, BCD), blk>>>(S, T);

    irfft_add_tc<<<dim3(8, 4, BCD), 256>>>(T, x, rb);

    ln_kernel<<<Bb * 1020, 256, LN_SMEM>>>(rb, gamma, beta, out);
}

// round 17
// speedup vs baseline: 1.1997x; 1.0723x over previous
#include <cuda_runtime.h>
#include <cuda_bf16.h>
#include <math.h>

#define Bb  2
#define Cc  128
#define Hh  256
#define Ww  510
#define WFD 256
#define HWD 130560   /* 256*510 */
#define BCD 256      /* Bb*Cc */

typedef unsigned int u32;
typedef unsigned long long u64;

__device__ __forceinline__ u64 pk2(float lo, float hi) {
    u64 r; asm("mov.b64 %0,{%1,%2};" : "=l"(r) : "f"(lo), "f"(hi)); return r;
}
__device__ __forceinline__ float2 up2(u64 v) {
    float2 r; asm("mov.b64 {%0,%1},%2;" : "=f"(r.x), "=f"(r.y) : "l"(v)); return r;
}
__device__ __forceinline__ u64 ffma2(u64 a, u64 b, u64 c) {
    u64 d; asm("fma.rn.f32x2 %0,%1,%2,%3;" : "=l"(d) : "l"(a), "l"(b), "l"(c)); return d;
}

// ---- tensor-core helpers -------------------------------------------------
__device__ __forceinline__ void mma_bf16(float* c, const u32* a, const u32* b) {
    asm("mma.sync.aligned.m16n8k16.row.col.f32.bf16.bf16.f32 "
        "{%0,%1,%2,%3},{%4,%5,%6,%7},{%8,%9},{%0,%1,%2,%3};"
        : "+f"(c[0]), "+f"(c[1]), "+f"(c[2]), "+f"(c[3])
        : "r"(a[0]), "r"(a[1]), "r"(a[2]), "r"(a[3]), "r"(b[0]), "r"(b[1]));
}
__device__ __forceinline__ void ldmA(u32* a, u32 addr) {
    asm volatile("ldmatrix.sync.aligned.m8n8.x4.shared.b16 {%0,%1,%2,%3},[%4];"
        : "=r"(a[0]), "=r"(a[1]), "=r"(a[2]), "=r"(a[3]) : "r"(addr));
}
__device__ __forceinline__ void ldmAT(u32* a, u32 addr) {
    asm volatile("ldmatrix.sync.aligned.m8n8.x4.trans.shared.b16 {%0,%1,%2,%3},[%4];"
        : "=r"(a[0]), "=r"(a[1]), "=r"(a[2]), "=r"(a[3]) : "r"(addr));
}
__device__ __forceinline__ void ldmB(u32* b, u32 addr) {
    asm volatile("ldmatrix.sync.aligned.m8n8.x2.shared.b16 {%0,%1},[%2];"
        : "=r"(b[0]), "=r"(b[1]) : "r"(addr));
}
__device__ __forceinline__ void ldmBT(u32* b, u32 addr) {
    asm volatile("ldmatrix.sync.aligned.m8n8.x2.trans.shared.b16 {%0,%1},[%2];"
        : "=r"(b[0]), "=r"(b[1]) : "r"(addr));
}
__device__ __forceinline__ u32 smaddr(const void* p) {
    return (u32)__cvta_generic_to_shared(p);
}
__device__ __forceinline__ void bsplit2(float a, float b, u32& hi, u32& lo) {
    __nv_bfloat16 ha = __float2bfloat16(a), hb = __float2bfloat16(b);
    hi = (u32)__bfloat16_as_ushort(ha) | ((u32)__bfloat16_as_ushort(hb) << 16);
    float ra = a - __bfloat162float(ha), rb = b - __bfloat162float(hb);
    __nv_bfloat16 la = __float2bfloat16(ra), lb = __float2bfloat16(rb);
    lo = (u32)__bfloat16_as_ushort(la) | ((u32)__bfloat16_as_ushort(lb) << 16);
}

// ---------------- scratch ----------------
// y as bf16 hi/lo planes, row-major: [sbc(512)][h(256)][wpair(256, 255 used)]
__device__ u32   d_yh [(size_t)512 * 65536];
__device__ u32   d_yl [(size_t)512 * 65536];
__device__ float2 d_Fg [(size_t)BCD * Hh * WFD];
__device__ float2 d_Fx [(size_t)BCD * Hh * WFD];
__device__ float2 d_Gg [(size_t)BCD * Hh * WFD];
__device__ float2 d_Gx [(size_t)BCD * Hh * WFD];
__device__ float2 d_Sb [(size_t)BCD * WFD * WFD];
__device__ float2 d_Tb [(size_t)BCD * Hh * WFD];
__device__ float  d_rb [(size_t)BCD * HWD];
__device__ float  d_rsq[BCD * Hh];
__device__ float  d_vp [(size_t)BCD * Hh * 64];
__device__ float2 d_W256[256];
// mma-fragment-order DFT tables
__device__ u64 d_DwFrh[32768], d_DwFrl[32768], d_DwFih[32768], d_DwFil[32768];
__device__ u64 d_CwF1h[32768], d_CwF1l[32768], d_CwF2h[32768], d_CwF2l[32768];
// conv weight A-fragment tables
__device__ u64 d_WF[2][4][2048];

__device__ __forceinline__ void sp_bits(float x, u32& hb, u32& lb) {
    __nv_bfloat16 h = __float2bfloat16(x);
    hb = (u32)__bfloat16_as_ushort(h);
    lb = (u32)__bfloat16_as_ushort(__float2bfloat16(x - __bfloat162float(h)));
}

// ---------------- table builder ----------------
__global__ void build_tables_kernel() {
    int idx = blockIdx.x * blockDim.x + threadIdx.x;
    int stride = gridDim.x * blockDim.x;
    float rsW = rsqrtf(510.0f);

    for (int i = idx; i < 32768; i += stride) {
        int lane = i & 31, kblk = (i >> 5) & 31, nblk = i >> 10;
        int v = nblk * 8 + (lane >> 2);
        u32 prh[2], prl[2], pih[2], pil[2];
#pragma unroll
        for (int reg = 0; reg < 2; reg++) {
            prh[reg] = prl[reg] = pih[reg] = pil[reg] = 0;
#pragma unroll
            for (int e = 0; e < 2; e++) {
                int w = kblk * 16 + (lane & 3) * 2 + e + reg * 8;
                float re = 0.f, im = 0.f;
                if (w < Ww) {
                    int m = (w * v) % Ww;
                    float s, c; sincospif(2.0f * (float)m / (float)Ww, &s, &c);
                    re = c * rsW; im = -s * rsW;
                }
                u32 hb, lb;
                sp_bits(re, hb, lb);
                prh[reg] |= hb << (16 * e); prl[reg] |= lb << (16 * e);
                sp_bits(im, hb, lb);
                pih[reg] |= hb << (16 * e); pil[reg] |= lb << (16 * e);
            }
        }
        d_DwFrh[i] = (u64)prh[0] | ((u64)prh[1] << 32);
        d_DwFrl[i] = (u64)prl[0] | ((u64)prl[1] << 32);
        d_DwFih[i] = (u64)pih[0] | ((u64)pih[1] << 32);
        d_DwFil[i] = (u64)pil[0] | ((u64)pil[1] << 32);
    }
    for (int i = idx; i < 32768; i += stride) {
        int lane = i & 31, kblk = (i >> 5) & 15, nblk = i >> 9;
        int w = nblk * 8 + (lane >> 2);
        u32 p1h[2], p1l[2], p2h[2], p2l[2];
#pragma unroll
        for (int reg = 0; reg < 2; reg++) {
            p1h[reg] = p1l[reg] = p2h[reg] = p2l[reg] = 0;
#pragma unroll
            for (int e = 0; e < 2; e++) {
                int v = kblk * 16 + (lane & 3) * 2 + e + reg * 8;
                float b1 = 0.f, b2 = 0.f;
                if (w < Ww) {
                    int m = (v * w) % Ww;
                    float s, c; sincospif(2.0f * (float)m / (float)Ww, &s, &c);
                    float sv = (v == 0 || v == 255) ? 1.0f : 2.0f;
                    b1 = sv * c * rsW; b2 = -sv * s * rsW;
                }
                u32 hb, lb;
                sp_bits(b1, hb, lb);
                p1h[reg] |= hb << (16 * e); p1l[reg] |= lb << (16 * e);
                sp_bits(b2, hb, lb);
                p2h[reg] |= hb << (16 * e); p2l[reg] |= lb << (16 * e);
            }
        }
        d_CwF1h[i] = (u64)p1h[0] | ((u64)p1h[1] << 32);
        d_CwF1l[i] = (u64)p1l[0] | ((u64)p1l[1] << 32);
        d_CwF2h[i] = (u64)p2h[0] | ((u64)p2h[1] << 32);
        d_CwF2l[i] = (u64)p2l[0] | ((u64)p2l[1] << 32);
    }
    for (int j = idx; j < 256; j += stride) {
        float s, c; sincospif(2.0f * (float)j / 256.0f, &s, &c);
        d_W256[j] = make_float2(c, -s);
    }
}

// ---------------- W pack ----------------
__global__ void pack_w_kernel(const float* __restrict__ wg, const float* __restrict__ wx) {
    int t = blockIdx.x * blockDim.x + threadIdx.x;
    if (t >= 4096) return;
    int wsel = t >> 11;
    int i = t & 2047;
    const float* W = wsel ? wx : wg;
    int lane = i & 31, kblk = (i >> 5) & 7, mblk = i >> 8;
    u32 qh[4], ql[4];
#pragma unroll
    for (int reg = 0; reg < 4; reg++) {
        int row = mblk * 16 + (lane >> 2) + 8 * (reg & 1);
        u32 hi = 0, lo = 0;
#pragma unroll
        for (int e = 0; e < 2; e++) {
            int k = kblk * 16 + (lane & 3) * 2 + e + 8 * (reg >> 1);
            float v = W[row * 128 + k];
            u32 hb, lb; sp_bits(v, hb, lb);
            hi |= hb << (16 * e); lo |= lb << (16 * e);
        }
        qh[reg] = hi; ql[reg] = lo;
    }
    d_WF[wsel][0][i] = (u64)qh[0] | ((u64)qh[1] << 32);
    d_WF[wsel][1][i] = (u64)ql[0] | ((u64)ql[1] << 32);
    d_WF[wsel][2][i] = (u64)qh[2] | ((u64)qh[3] << 32);
    d_WF[wsel][3][i] = (u64)ql[2] | ((u64)ql[3] << 32);
}

__device__ __forceinline__ float sigm(float v) { return 1.f / (1.f + expf(-v)); }

#define PITS 72
#define SSZ  (32 * PITS)

// -------- 1x1 conv — merged g/x; epilogue writes bf16 hi/lo planes ------
__global__ void __launch_bounds__(256, 2) conv_tc(
    const float* __restrict__ g, const float* __restrict__ x,
    const float* __restrict__ bg, const float* __restrict__ bx)
{
    __shared__ __nv_bfloat16 sXh[2][SSZ], sXl[2][SSZ];
    int z = blockIdx.z;
    int b = z & 1, wsel = z >> 1;
    const float* Xb = (wsel ? x : g) + (size_t)b * Cc * HWD;
    const float* bias = wsel ? bx : bg;
    int base_bc = wsel * 256 + b * 128;
    int n0 = blockIdx.x * 64, m0 = blockIdx.y * 64;
    int t = threadIdx.x, lane = t & 31, wid = t >> 5;
    int wm = (wid >> 2) * 32, wn = (wid & 3) * 16;
    int g4 = lane >> 2, tc4 = lane & 3;

    float acc[2][2][4];
#pragma unroll
    for (int i = 0; i < 2; i++)
#pragma unroll
        for (int j = 0; j < 2; j++)
#pragma unroll
            for (int q = 0; q < 4; q++) acc[i][j][q] = 0.f;

    int kB = (lane & 7) + ((lane >> 3) & 1) * 8;
    int scB = t & 31, srB = t >> 5;
    int mblk_base = (m0 + wm) >> 4;

    float2 xv[4];
#define CONV_LOAD(K0) { \
    _Pragma("unroll") \
    for (int i = 0; i < 4; i++) \
        xv[i] = *(const float2*)&Xb[(size_t)((K0) + srB + i * 8) * HWD + n0 + 2 * scB]; }
#define CONV_STORE(BF) { \
    _Pragma("unroll") \
    for (int i = 0; i < 4; i++) { \
        u32 hi, lo; bsplit2(xv[i].x, xv[i].y, hi, lo); \
        int so = (srB + i * 8) * PITS + 2 * scB; \
        *(u32*)&sXh[BF][so] = hi; *(u32*)&sXl[BF][so] = lo; \
    } }

    CONV_LOAD(0)
    CONV_STORE(0)
    __syncthreads();
    for (int it = 0; it < 4; it++) {
        int buf = it & 1;
        if (it < 3) CONV_LOAD((it + 1) * 32)
        u32 aXh = smaddr(sXh[buf]), aXl = smaddr(sXl[buf]);
#pragma unroll
        for (int ks = 0; ks < 2; ks++) {
            int kb = ks * 16;
            int kblk = it * 2 + ks;
            u32 ah[2][4], al[2][4];
#pragma unroll
            for (int tm = 0; tm < 2; tm++) {
                size_t bi = ((size_t)((mblk_base + tm) * 8 + kblk) << 5) + lane;
                u64 v;
                v = d_WF[wsel][0][bi]; ah[tm][0] = (u32)v; ah[tm][1] = (u32)(v >> 32);
                v = d_WF[wsel][2][bi]; ah[tm][2] = (u32)v; ah[tm][3] = (u32)(v >> 32);
                v = d_WF[wsel][1][bi]; al[tm][0] = (u32)v; al[tm][1] = (u32)(v >> 32);
                v = d_WF[wsel][3][bi]; al[tm][2] = (u32)v; al[tm][3] = (u32)(v >> 32);
            }
            u32 bh[2][2], bl[2][2];
#pragma unroll
            for (int tn = 0; tn < 2; tn++) {
                u32 off = ((kb + kB) * PITS + wn + 8 * tn) * 2;
                ldmBT(bh[tn], aXh + off);
                ldmBT(bl[tn], aXl + off);
            }
#pragma unroll
            for (int tm = 0; tm < 2; tm++)
#pragma unroll
                for (int tn = 0; tn < 2; tn++) {
                    mma_bf16(acc[tm][tn], ah[tm], bh[tn]);
                    mma_bf16(acc[tm][tn], ah[tm], bl[tn]);
                    mma_bf16(acc[tm][tn], al[tm], bh[tn]);
                }
        }
        if (it < 3) CONV_STORE(buf ^ 1)
        __syncthreads();
    }
#undef CONV_LOAD
#undef CONV_STORE
#pragma unroll
    for (int tm = 0; tm < 2; tm++)
#pragma unroll
        for (int tn = 0; tn < 2; tn++) {
            int cout = m0 + wm + 16 * tm + g4;
            int col = n0 + wn + 8 * tn + 2 * tc4;   // even; pair stays in one h-row
            u32 h = (u32)col / 510u;
            u32 w = (u32)col - h * 510u;
            size_t pidx = (((size_t)(base_bc + cout)) * 256 + h) * 256 + (w >> 1);
            float bv0 = bias[cout], bv1 = bias[cout + 8];
            u32 hi, lo;
            bsplit2(acc[tm][tn][0] + bv0, acc[tm][tn][1] + bv0, hi, lo);
            d_yh[pidx] = hi; d_yl[pidx] = lo;
            size_t pidx2 = pidx + (size_t)8 * 65536;   // cout+8
            bsplit2(acc[tm][tn][2] + bv1, acc[tm][tn][3] + bv1, hi, lo);
            d_yh[pidx2] = hi; d_yl[pidx2] = lo;
        }
}

// ------- rfft along W — R14 smem-staged, A from bf16 planes (no bsplit) -------
#define PIT  40
#define ASZ  (64 * PIT)
__global__ void __launch_bounds__(256, 2) rfftw_tc(
    float2* __restrict__ Fg, float2* __restrict__ Fx)
{
    __shared__ __nv_bfloat16 sAh[2][ASZ], sAl[2][ASZ];
    int z = blockIdx.z;                 // sel*256 + bc == plane index
    float2* Cp = ((z >> 8) ? Fx : Fg) + (size_t)(z & 255) * Hh * WFD;
    int n0 = blockIdx.x * 64, m0 = blockIdx.y * 64;
    int t = threadIdx.x, lane = t & 31, wid = t >> 5;
    int wm = (wid >> 2) * 32, wn = (wid & 3) * 16;
    int g = lane >> 2, tc = lane & 3;

    float cre[2][2][4], cim[2][2][4];
#pragma unroll
    for (int i = 0; i < 2; i++)
#pragma unroll
        for (int j = 0; j < 2; j++)
#pragma unroll
            for (int q = 0; q < 4; q++) { cre[i][j][q] = 0.f; cim[i][j][q] = 0.f; }

    int lrA = lane & 15, lkA = (lane >> 4) * 8;
    int sc = t & 15, sr = t >> 4;
    int nblk0 = (n0 + wn) >> 3;

    u32 ahv[4], alv[4];
#define RFW_LOAD(K0) { \
    _Pragma("unroll") \
    for (int i = 0; i < 4; i++) { \
        int r = sr + i * 16; int w = (K0) + 2 * sc; \
        if (w < Ww) { \
            size_t pi = (((size_t)z) * 256 + m0 + r) * 256 + (w >> 1); \
            ahv[i] = d_yh[pi]; alv[i] = d_yl[pi]; \
        } else { ahv[i] = 0; alv[i] = 0; } \
    } }
#define RFW_STORE(BF) { \
    _Pragma("unroll") \
    for (int i = 0; i < 4; i++) { \
        int so = (sr + i * 16) * PIT + 2 * sc; \
        *(u32*)&sAh[BF][so] = ahv[i]; *(u32*)&sAl[BF][so] = alv[i]; \
    } }

    RFW_LOAD(0)
    RFW_STORE(0)
    __syncthreads();
    for (int it = 0; it < 16; it++) {
        int buf = it & 1;
        if (it < 15) RFW_LOAD((it + 1) * 32)
        u32 aAh = smaddr(sAh[buf]), aAl = smaddr(sAl[buf]);
#pragma unroll
        for (int ks = 0; ks < 2; ks++) {
            int kb = ks * 16;
            int kblk = it * 2 + ks;
            u32 ah[2][4], al[2][4];
#pragma unroll
            for (int tm = 0; tm < 2; tm++) {
                u32 off = ((wm + 16 * tm + lrA) * PIT + kb + lkA) * 2;
                ldmA(ah[tm], aAh + off);
                ldmA(al[tm], aAl + off);
            }
            u32 brh[2][2], brl[2][2], bih[2][2], bil[2][2];
#pragma unroll
            for (int tn = 0; tn < 2; tn++) {
                size_t bi = ((size_t)((nblk0 + tn) * 32 + kblk) << 5) + lane;
                u64 v;
                v = d_DwFrh[bi]; brh[tn][0] = (u32)v; brh[tn][1] = (u32)(v >> 32);
                v = d_DwFrl[bi]; brl[tn][0] = (u32)v; brl[tn][1] = (u32)(v >> 32);
                v = d_DwFih[bi]; bih[tn][0] = (u32)v; bih[tn][1] = (u32)(v >> 32);
                v = d_DwFil[bi]; bil[tn][0] = (u32)v; bil[tn][1] = (u32)(v >> 32);
            }
#pragma unroll
            for (int tm = 0; tm < 2; tm++)
#pragma unroll
                for (int tn = 0; tn < 2; tn++) {
                    mma_bf16(cre[tm][tn], ah[tm], brh[tn]);
                    mma_bf16(cre[tm][tn], ah[tm], brl[tn]);
                    mma_bf16(cre[tm][tn], al[tm], brh[tn]);
                    mma_bf16(cim[tm][tn], ah[tm], bih[tn]);
                    mma_bf16(cim[tm][tn], ah[tm], bil[tn]);
                    mma_bf16(cim[tm][tn], al[tm], bih[tn]);
                }
        }
        if (it < 15) RFW_STORE(buf ^ 1)
        __syncthreads();
    }
#undef RFW_LOAD
#undef RFW_STORE
#pragma unroll
    for (int tm = 0; tm < 2; tm++)
#pragma unroll
        for (int tn = 0; tn < 2; tn++) {
            int r0 = m0 + wm + 16 * tm + g;
            int col = n0 + wn + 8 * tn + 2 * tc;
            float4 v0 = make_float4(cre[tm][tn][0], cim[tm][tn][0], cre[tm][tn][1], cim[tm][tn][1]);
            *(float4*)&Cp[(size_t)r0 * WFD + col] = v0;
            float4 v1 = make_float4(cre[tm][tn][2], cim[tm][tn][2], cre[tm][tn][3], cim[tm][tn][3]);
            *(float4*)&Cp[(size_t)(r0 + 8) * WFD + col] = v1;
        }
}

// ------- irfft along W + residual — R14 form ----
__global__ void __launch_bounds__(256, 2) irfft_add_tc(
    const float2* __restrict__ T, const float* __restrict__ x, float* __restrict__ r)
{
    __shared__ __nv_bfloat16 sArh[2][ASZ], sArl[2][ASZ], sAih[2][ASZ], sAil[2][ASZ];
    int bc = blockIdx.z;
    const float2* Ap = T + (size_t)bc * 65536;
    int n0 = blockIdx.x * 64, m0 = blockIdx.y * 64;
    int t = threadIdx.x, lane = t & 31, wid = t >> 5;
    int wm = (wid >> 2) * 32, wn = (wid & 3) * 16;
    int g = lane >> 2, tc = lane & 3;

    float acc[2][2][4];
#pragma unroll
    for (int i = 0; i < 2; i++)
#pragma unroll
        for (int j = 0; j < 2; j++)
#pragma unroll
            for (int q = 0; q < 4; q++) acc[i][j][q] = 0.f;

    int lrA = lane & 15, lkA = (lane >> 4) * 8;
    int sc = t & 15, sr = t >> 4;
    int nblk0 = (n0 + wn) >> 3;

    float4 va[4];
#define IRF_LOAD(K0) { \
    _Pragma("unroll") \
    for (int i = 0; i < 4; i++) { \
        int rr = sr + i * 16; \
        va[i] = *(const float4*)&Ap[(size_t)(m0 + rr) * 256 + (K0) + 2 * sc]; \
    } }
#define IRF_STORE(BF) { \
    _Pragma("unroll") \
    for (int i = 0; i < 4; i++) { \
        int so = (sr + i * 16) * PIT + 2 * sc; \
        u32 hi, lo; \
        bsplit2(va[i].x, va[i].z, hi, lo); \
        *(u32*)&sArh[BF][so] = hi; *(u32*)&sArl[BF][so] = lo; \
        bsplit2(va[i].y, va[i].w, hi, lo); \
        *(u32*)&sAih[BF][so] = hi; *(u32*)&sAil[BF][so] = lo; \
    } }

    IRF_LOAD(0)
    IRF_STORE(0)
    __syncthreads();
    for (int it = 0; it < 8; it++) {
        int buf = it & 1;
        if (it < 7) IRF_LOAD((it + 1) * 32)
        u32 aArh = smaddr(sArh[buf]), aArl = smaddr(sArl[buf]);
        u32 aAih = smaddr(sAih[buf]), aAil = smaddr(sAil[buf]);
#pragma unroll
        for (int ks = 0; ks < 2; ks++) {
            int kb = ks * 16;
            int kblk = it * 2 + ks;
            u32 arh[2][4], arl[2][4], aih[2][4], ail[2][4];
#pragma unroll
            for (int tm = 0; tm < 2; tm++) {
                u32 off = ((wm + 16 * tm + lrA) * PIT + kb + lkA) * 2;
                ldmA(arh[tm], aArh + off);
                ldmA(arl[tm], aArl + off);
                ldmA(aih[tm], aAih + off);
                ldmA(ail[tm], aAil + off);
            }
            u32 b1h[2][2], b1l[2][2], b2h[2][2], b2l[2][2];
#pragma unroll
            for (int tn = 0; tn < 2; tn++) {
                size_t bi = ((size_t)((nblk0 + tn) * 16 + kblk) << 5) + lane;
                u64 v;
                v = d_CwF1h[bi]; b1h[tn][0] = (u32)v; b1h[tn][1] = (u32)(v >> 32);
                v = d_CwF1l[bi]; b1l[tn][0] = (u32)v; b1l[tn][1] = (u32)(v >> 32);
                v = d_CwF2h[bi]; b2h[tn][0] = (u32)v; b2h[tn][1] = (u32)(v >> 32);
                v = d_CwF2l[bi]; b2l[tn][0] = (u32)v; b2l[tn][1] = (u32)(v >> 32);
            }
#pragma unroll
            for (int tm = 0; tm < 2; tm++)
#pragma unroll
                for (int tn = 0; tn < 2; tn++) {
                    mma_bf16(acc[tm][tn], arh[tm], b1h[tn]);
                    mma_bf16(acc[tm][tn], arh[tm], b1l[tn]);
                    mma_bf16(acc[tm][tn], arl[tm], b1h[tn]);
                    mma_bf16(acc[tm][tn], aih[tm], b2h[tn]);
                    mma_bf16(acc[tm][tn], aih[tm], b2l[tn]);
                    mma_bf16(acc[tm][tn], ail[tm], b2h[tn]);
                }
        }
        if (it < 7) IRF_STORE(buf ^ 1)
        __syncthreads();
    }
#undef IRF_LOAD
#undef IRF_STORE
#pragma unroll
    for (int tm = 0; tm < 2; tm++)
#pragma unroll
        for (int tn = 0; tn < 2; tn++) {
            int col = n0 + wn + 8 * tn + 2 * tc;
            if (col < Ww) {
                int r0 = m0 + wm + 16 * tm + g;
                size_t i0 = (size_t)bc * HWD + (size_t)r0 * Ww + col;
                size_t i1 = i0 + (size_t)8 * Ww;
                float2 xv = *(const float2*)&x[i0];
                *(float2*)&r[i0] = make_float2(acc[tm][tn][0] + xv.x, acc[tm][tn][1] + xv.y);
                xv = *(const float2*)&x[i1];
                *(float2*)&r[i1] = make_float2(acc[tm][tn][2] + xv.x, acc[tm][tn][3] + xv.y);
            }
        }
}

// ---------------- forward ffth (merged g/x) + fused variance partials ------
__global__ void __launch_bounds__(256) ffth_fwd(
    const float2* __restrict__ Fg, const float2* __restrict__ Fx,
    float2* __restrict__ Gg, float2* __restrict__ Gx,
    const float2* __restrict__ fg, const float2* __restrict__ fx,
    float* __restrict__ vp)
{
    __shared__ float2 Xs[256][17];
    __shared__ float2 Ws[256];
    int yz = blockIdx.y;
    int sel = yz >> 8, bc = yz & 255;
    const float2* inp = (sel ? Fx : Fg) + (size_t)bc * 65536;
    float2* outp = (sel ? Gx : Gg) + (size_t)bc * 65536;
    const float2* filt = sel ? fx : fg;
    int v0 = blockIdx.x * 16;
    int tx = threadIdx.x;
    int ty = threadIdx.y;
    int t = ty * 16 + tx;

    {
        float2 w = d_W256[t];
        Ws[t] = w;
    }
#pragma unroll
    for (int i = 0; i < 16; i++) {
        int h = i * 16 + ty;
        Xs[h][tx] = inp[(size_t)h * 256 + v0 + tx];
    }
    __syncthreads();

    float2 rr[16];
    {
        u64 tw[16];
#pragma unroll
        for (int n1 = 0; n1 < 16; n1++) {
            float2 w = Ws[(n1 * ty * 16) & 255];
            tw[n1] = pk2(w.x, w.y);
        }
#pragma unroll
        for (int n2 = 0; n2 < 16; n2++) {
            u64 accA = 0ull, accB = 0ull;
#pragma unroll
            for (int n1 = 0; n1 < 16; n1++) {
                float2 xv = Xs[16 * n1 + n2][tx];
                u64 xp = pk2(xv.x, xv.y);
                u64 xq = pk2(xv.y, xv.x);
                accA = ffma2(xp, tw[n1], accA);
                accB = ffma2(xq, tw[n1], accB);
            }
            float2 a = up2(accA), b = up2(accB);
            float ar = a.x - a.y, ai = b.x + b.y;
            float2 tm = Ws[(n2 * ty) & 255];
            rr[n2] = make_float2(ar * tm.x - ai * tm.y, ar * tm.y + ai * tm.x);
        }
    }
    __syncthreads();
#pragma unroll
    for (int n2 = 0; n2 < 16; n2++)
        Xs[ty * 16 + n2][tx] = rr[n2];
    __syncthreads();

    {
        u64 tw[16];
#pragma unroll
        for (int n2 = 0; n2 < 16; n2++) {
            float2 w = Ws[(n2 * ty * 16) & 255];
            tw[n2] = pk2(w.x, w.y);
        }
        int c = bc & (Cc - 1);
#pragma unroll
        for (int k1 = 0; k1 < 16; k1++) {
            u64 accA = 0ull, accB = 0ull;
#pragma unroll
            for (int n2 = 0; n2 < 16; n2++) {
                float2 xv = Xs[k1 * 16 + n2][tx];
                u64 xp = pk2(xv.x, xv.y);
                u64 xq = pk2(xv.y, xv.x);
                accA = ffma2(xp, tw[n2], accA);
                accB = ffma2(xq, tw[n2], accB);
            }
            float2 a = up2(accA), b = up2(accB);
            int u = k1 + 16 * ty;
            float2 v = make_float2((a.x - a.y) * 0.0625f, (b.x + b.y) * 0.0625f);
            float2 wc = filt[((size_t)c * Hh + u) * WFD + v0 + tx];
            v = make_float2(v.x * wc.x - v.y * wc.y, v.x * wc.y + v.y * wc.x);
            outp[(size_t)u * 256 + v0 + tx] = v;
            if (sel == 0) {
                float sre = v.x, sim = v.y, ssq = v.x * v.x + v.y * v.y;
#pragma unroll
                for (int msk = 8; msk >= 1; msk >>= 1) {
                    sre += __shfl_xor_sync(0xFFFFFFFFu, sre, msk);
                    sim += __shfl_xor_sync(0xFFFFFFFFu, sim, msk);
                    ssq += __shfl_xor_sync(0xFFFFFFFFu, ssq, msk);
                }
                if (tx == 0) {
                    size_t idx = (((size_t)bc * 256 + u) * 16 + blockIdx.x) * 4;
                    *(float4*)&vp[idx] = make_float4(sre, sim, ssq, 0.f);
                }
            }
        }
    }
}

// ------- variance finalize -------
__global__ void var_fin(const float* __restrict__ vp, float* __restrict__ rsq)
{
    int row = blockIdx.x * 256 + threadIdx.x;
    const float4* p = (const float4*)(vp + (size_t)row * 64);
    float sre = 0.f, sim = 0.f, ssq = 0.f;
#pragma unroll
    for (int i = 0; i < 16; i++) {
        float4 v = p[i];
        sre += v.x; sim += v.y; ssq += v.z;
    }
    float mr = sre * (1.f / 256.f), mi = sim * (1.f / 256.f);
    float var = ssq * (1.f / 256.f) - mr * mr - mi * mi;
    rsq[row] = 1.f / sqrtf(6.283185307179586f * var);
}

// ---------------- inverse ffth ----------------
__global__ void __launch_bounds__(256) ffth_inv(
    const float2* __restrict__ in, float2* __restrict__ out)
{
    __shared__ float2 Xs[256][17];
    __shared__ float2 Ws[256];
    int bc = blockIdx.y;
    int v0 = blockIdx.x * 16;
    int tx = threadIdx.x;
    int ty = threadIdx.y;
    int t = ty * 16 + tx;
    const float2* inp = in + (size_t)bc * 65536 + v0;
    float2* outp = out + (size_t)bc * 65536 + v0;

    {
        float2 w = d_W256[t];
        w.y = -w.y;
        Ws[t] = w;
    }
#pragma unroll
    for (int i = 0; i < 16; i++) {
        int h = i * 16 + ty;
        Xs[h][tx] = inp[(size_t)h * 256 + tx];
    }
    __syncthreads();

    float2 rr[16];
    {
        u64 tw[16];
#pragma unroll
        for (int n1 = 0; n1 < 16; n1++) {
            float2 w = Ws[(n1 * ty * 16) & 255];
            tw[n1] = pk2(w.x, w.y);
        }
#pragma unroll
        for (int n2 = 0; n2 < 16; n2++) {
            u64 accA = 0ull, accB = 0ull;
#pragma unroll
            for (int n1 = 0; n1 < 16; n1++) {
                float2 xv = Xs[16 * n1 + n2][tx];
                u64 xp = pk2(xv.x, xv.y);
                u64 xq = pk2(xv.y, xv.x);
                accA = ffma2(xp, tw[n1], accA);
                accB = ffma2(xq, tw[n1], accB);
            }
            float2 a = up2(accA), b = up2(accB);
            float ar = a.x - a.y, ai = b.x + b.y;
            float2 tm = Ws[(n2 * ty) & 255];
            rr[n2] = make_float2(ar * tm.x - ai * tm.y, ar * tm.y + ai * tm.x);
        }
    }
    __syncthreads();
#pragma unroll
    for (int n2 = 0; n2 < 16; n2++)
        Xs[ty * 16 + n2][tx] = rr[n2];
    __syncthreads();

    {
        u64 tw[16];
#pragma unroll
        for (int n2 = 0; n2 < 16; n2++) {
            float2 w = Ws[(n2 * ty * 16) & 255];
            tw[n2] = pk2(w.x, w.y);
        }
#pragma unroll
        for (int k1 = 0; k1 < 16; k1++) {
            u64 accA = 0ull, accB = 0ull;
#pragma unroll
            for (int n2 = 0; n2 < 16; n2++) {
                float2 xv = Xs[k1 * 16 + n2][tx];
                u64 xp = pk2(xv.x, xv.y);
                u64 xq = pk2(xv.y, xv.x);
                accA = ffma2(xp, tw[n2], accA);
                accB = ffma2(xq, tw[n2], accB);
            }
            float2 a = up2(accA), b = up2(accB);
            int u = k1 + 16 * ty;
            float2 v = make_float2((a.x - a.y) * 0.0625f, (b.x + b.y) * 0.0625f);
            outp[(size_t)u * 256 + tx] = v;
        }
    }
}

// ------- scores — HMMA complex, double-buffered (dynamic smem) -------
__global__ void __launch_bounds__(256) scores_tc(
    const float2* __restrict__ Gb, const float2* __restrict__ Xb,
    const float* __restrict__ rsq, float2* __restrict__ Sb)
{
    extern __shared__ __nv_bfloat16 dynS[];
    __nv_bfloat16* sGrh = dynS;
    __nv_bfloat16* sGrl = sGrh + 2 * SSZ;
    __nv_bfloat16* sGih = sGrl + 2 * SSZ;
    __nv_bfloat16* sGil = sGih + 2 * SSZ;
    __nv_bfloat16* sXrh = sGil + 2 * SSZ;
    __nv_bfloat16* sXrl = sXrh + 2 * SSZ;
    __nv_bfloat16* sXih = sXrl + 2 * SSZ;
    __nv_bfloat16* sXil = sXih + 2 * SSZ;
    int bc = blockIdx.z;
    const float2* Ap = Gb + (size_t)bc * 65536;
    const float2* Bp = Xb + (size_t)bc * 65536;
    float2* Cp = Sb + (size_t)bc * 65536;
    int n0 = blockIdx.x * 64, m0 = blockIdx.y * 64;
    int t = threadIdx.x, lane = t & 31, wid = t >> 5;
    int wm = (wid >> 2) * 32, wn = (wid & 3) * 16;
    int g = lane >> 2, tc4 = lane & 3;

    float are[2][2][4], aim[2][2][4];
#pragma unroll
    for (int i = 0; i < 2; i++)
#pragma unroll
        for (int j = 0; j < 2; j++)
#pragma unroll
            for (int q = 0; q < 4; q++) { are[i][j][q] = 0.f; aim[i][j][q] = 0.f; }

    int kA = (lane & 7) + ((lane >> 4) & 1) * 8;
    int mA = ((lane >> 3) & 1) * 8;
    int kB = (lane & 7) + ((lane >> 3) & 1) * 8;
    int sc = t & 31, sr = t >> 5;

    float4 vA[4], vB[4];
#define SCR_LOAD(K0) { \
    _Pragma("unroll") \
    for (int i = 0; i < 4; i++) { \
        int k = sr + i * 8; \
        vA[i] = *(const float4*)&Ap[(size_t)((K0) + k) * 256 + m0 + 2 * sc]; \
        vB[i] = *(const float4*)&Bp[(size_t)((K0) + k) * 256 + n0 + 2 * sc]; \
    } }
#define SCR_STORE(BF) { \
    _Pragma("unroll") \
    for (int i = 0; i < 4; i++) { \
        int so = (BF) * SSZ + (sr + i * 8) * PITS + 2 * sc; \
        u32 hi, lo; \
        bsplit2(vA[i].x, vA[i].z, hi, lo); *(u32*)&sGrh[so] = hi; *(u32*)&sGrl[so] = lo; \
        bsplit2(vA[i].y, vA[i].w, hi, lo); *(u32*)&sGih[so] = hi; *(u32*)&sGil[so] = lo; \
        bsplit2(vB[i].x, vB[i].z, hi, lo); *(u32*)&sXrh[so] = hi; *(u32*)&sXrl[so] = lo; \
        bsplit2(vB[i].y, vB[i].w, hi, lo); *(u32*)&sXih[so] = hi; *(u32*)&sXil[so] = lo; \
    } }

    SCR_LOAD(0)
    SCR_STORE(0)
    __syncthreads();
    for (int it = 0; it < 8; it++) {
        int buf = it & 1;
        if (it < 7) SCR_LOAD((it + 1) * 32)
        u32 aGrh = smaddr(sGrh + buf * SSZ), aGrl = smaddr(sGrl + buf * SSZ);
        u32 aGih = smaddr(sGih + buf * SSZ), aGil = smaddr(sGil + buf * SSZ);
        u32 aXrh = smaddr(sXrh + buf * SSZ), aXrl = smaddr(sXrl + buf * SSZ);
        u32 aXih = smaddr(sXih + buf * SSZ), aXil = smaddr(sXil + buf * SSZ);
#pragma unroll
        for (int ks = 0; ks < 2; ks++) {
            int kb = ks * 16;
            u32 grh[2][4], grl[2][4], gih[2][4], gil[2][4];
#pragma unroll
            for (int tm = 0; tm < 2; tm++) {
                u32 off = ((kb + kA) * PITS + wm + 16 * tm + mA) * 2;
                ldmAT(grh[tm], aGrh + off);
                ldmAT(grl[tm], aGrl + off);
                ldmAT(gih[tm], aGih + off);
                ldmAT(gil[tm], aGil + off);
            }
            u32 xrh[2][2], xrl[2][2], xih[2][2], xil[2][2];
#pragma unroll
            for (int tn = 0; tn < 2; tn++) {
                u32 off = ((kb + kB) * PITS + wn + 8 * tn) * 2;
                ldmBT(xrh[tn], aXrh + off);
                ldmBT(xrl[tn], aXrl + off);
                ldmBT(xih[tn], aXih + off);
                ldmBT(xil[tn], aXil + off);
            }
#pragma unroll
            for (int tm = 0; tm < 2; tm++) {
                u32 nih[4], nil_[4];
#pragma unroll
                for (int q = 0; q < 4; q++) {
                    nih[q]  = gih[tm][q] ^ 0x80008000u;
                    nil_[q] = gil[tm][q] ^ 0x80008000u;
                }
#pragma unroll
                for (int tn = 0; tn < 2; tn++) {
                    mma_bf16(are[tm][tn], grh[tm], xrh[tn]);
                    mma_bf16(are[tm][tn], grh[tm], xrl[tn]);
                    mma_bf16(are[tm][tn], grl[tm], xrh[tn]);
                    mma_bf16(are[tm][tn], nih,     xih[tn]);
                    mma_bf16(are[tm][tn], nih,     xil[tn]);
                    mma_bf16(are[tm][tn], nil_,    xih[tn]);
                    mma_bf16(aim[tm][tn], grh[tm], xih[tn]);
                    mma_bf16(aim[tm][tn], grh[tm], xil[tn]);
                    mma_bf16(aim[tm][tn], grl[tm], xih[tn]);
                    mma_bf16(aim[tm][tn], gih[tm], xrh[tn]);
                    mma_bf16(aim[tm][tn], gih[tm], xrl[tn]);
                    mma_bf16(aim[tm][tn], gil[tm], xrh[tn]);
                }
            }
        }
        if (it < 7) SCR_STORE(buf ^ 1)
        __syncthreads();
    }
#undef SCR_LOAD
#undef SCR_STORE
#pragma unroll
    for (int tm = 0; tm < 2; tm++)
#pragma unroll
        for (int tn = 0; tn < 2; tn++) {
            int r0 = m0 + wm + 16 * tm + g;
            int col = n0 + wn + 8 * tn + 2 * tc4;
            float s0 = rsq[bc * Hh + r0], s1 = rsq[bc * Hh + r0 + 8];
            float4 o0 = make_float4(
                sigm(are[tm][tn][0] * s0), sigm(aim[tm][tn][0] * s0),
                sigm(are[tm][tn][1] * s0), sigm(aim[tm][tn][1] * s0));
            *(float4*)&Cp[(size_t)r0 * 256 + col] = o0;
            float4 o1 = make_float4(
                sigm(are[tm][tn][2] * s1), sigm(aim[tm][tn][2] * s1),
                sigm(are[tm][tn][3] * s1), sigm(aim[tm][tn][3] * s1));
            *(float4*)&Cp[(size_t)(r0 + 8) * 256 + col] = o1;
        }
}

// ------- channel LayerNorm — float4 smem-tiled -------
#define LN_SMEM ((128 * 32 + 2 * 8 * 32 + 64) * 16)
__global__ void __launch_bounds__(256) ln_kernel(
    const float* __restrict__ r, const float* __restrict__ gamma,
    const float* __restrict__ beta, float* __restrict__ out)
{
    extern __shared__ float4 lns[];
    float4* tile = lns;
    float4* ps   = tile + 128 * 32;
    float4* qs   = ps + 8 * 32;
    float4* muv  = qs + 8 * 32;
    float4* invv = muv + 32;
    int blk = blockIdx.x;
    int b = blk / 1020;
    int w0 = (blk - b * 1020) * 128;
    int t = threadIdx.x;
    int w4 = t & 31, cq = t >> 5;

    float4 s = make_float4(0.f, 0.f, 0.f, 0.f);
    float4 q = make_float4(0.f, 0.f, 0.f, 0.f);
#pragma unroll
    for (int c0 = 0; c0 < 128; c0 += 8) {
        int c = c0 + cq;
        float4 v = *(const float4*)&r[(size_t)(b * Cc + c) * HWD + w0 + w4 * 4];
        tile[c * 32 + w4] = v;
        s.x += v.x; s.y += v.y; s.z += v.z; s.w += v.w;
        q.x += v.x * v.x; q.y += v.y * v.y; q.z += v.z * v.z; q.w += v.w * v.w;
    }
    ps[cq * 32 + w4] = s;
    qs[cq * 32 + w4] = q;
    __syncthreads();
    if (t < 32) {
        float4 S = make_float4(0.f, 0.f, 0.f, 0.f);
        float4 Q = make_float4(0.f, 0.f, 0.f, 0.f);
#pragma unroll
        for (int i = 0; i < 8; i++) {
            float4 a = ps[i * 32 + t];
            S.x += a.x; S.y += a.y; S.z += a.z; S.w += a.w;
            a = qs[i * 32 + t];
            Q.x += a.x; Q.y += a.y; Q.z += a.z; Q.w += a.w;
        }
        float4 m = make_float4(S.x * (1.f / 128.f), S.y * (1.f / 128.f),
                               S.z * (1.f / 128.f), S.w * (1.f / 128.f));
        float4 iv;
        iv.x = rsqrtf(Q.x * (1.f / 128.f) - m.x * m.x + 1e-6f);
        iv.y = rsqrtf(Q.y * (1.f / 128.f) - m.y * m.y + 1e-6f);
        iv.z = rsqrtf(Q.z * (1.f / 128.f) - m.z * m.z + 1e-6f);
        iv.w = rsqrtf(Q.w * (1.f / 128.f) - m.w * m.w + 1e-6f);
        muv[t] = m;
        invv[t] = iv;
    }
    __syncthreads();
    float4 m = muv[w4], iv = invv[w4];
#pragma unroll
    for (int c0 = 0; c0 < 128; c0 += 8) {
        int c = c0 + cq;
        float4 v = tile[c * 32 + w4];
        float gm = gamma[c], bt = beta[c];
        float4 o;
        o.x = gm * (v.x - m.x) * iv.x + bt;
        o.y = gm * (v.y - m.y) * iv.y + bt;
        o.z = gm * (v.z - m.z) * iv.z + bt;
        o.w = gm * (v.w - m.w) * iv.w + bt;
        *(float4*)&out[(size_t)(b * Cc + c) * HWD + w0 + w4 * 4] = o;
    }
}

// ---------------- launch ----------------
extern "C" void kernel_launch(void* const* d_in, const int* in_sizes, int n_in,
                              void* d_out, int out_size)
{
    (void)in_sizes; (void)n_in; (void)out_size;
    const float*  g     = (const float*)d_in[0];
    const float*  x     = (const float*)d_in[1];
    const float*  wg    = (const float*)d_in[2];
    const float*  bg    = (const float*)d_in[3];
    const float*  wx    = (const float*)d_in[4];
    const float*  bx    = (const float*)d_in[5];
    const float2* fg    = (const float2*)d_in[6];
    const float2* fx    = (const float2*)d_in[7];
    const float*  gamma = (const float*)d_in[8];
    const float*  beta  = (const float*)d_in[9];
    float* out = (float*)d_out;

    float *rb, *rsq, *vp;
    float2 *Fg, *Fx, *Gg, *Gx, *S, *T;
    cudaGetSymbolAddress((void**)&Fg,  d_Fg);
    cudaGetSymbolAddress((void**)&Fx,  d_Fx);
    cudaGetSymbolAddress((void**)&Gg,  d_Gg);
    cudaGetSymbolAddress((void**)&Gx,  d_Gx);
    cudaGetSymbolAddress((void**)&S,   d_Sb);
    cudaGetSymbolAddress((void**)&T,   d_Tb);
    cudaGetSymbolAddress((void**)&rb,  d_rb);
    cudaGetSymbolAddress((void**)&rsq, d_rsq);
    cudaGetSymbolAddress((void**)&vp,  d_vp);

    static int attr_done = 0;
    if (!attr_done) {
        cudaFuncSetAttribute(scores_tc, cudaFuncAttributeMaxDynamicSharedMemorySize,
                             16 * SSZ * 2);
        cudaFuncSetAttribute(ln_kernel, cudaFuncAttributeMaxDynamicSharedMemorySize,
                             LN_SMEM);
        attr_done = 1;
    }

    dim3 blk(16, 16);

    build_tables_kernel<<<512, 256>>>();
    pack_w_kernel<<<16, 256>>>(wg, wx);

    conv_tc<<<dim3(HWD / 64, 2, 2 * Bb), 256>>>(g, x, bg, bx);

    rfftw_tc<<<dim3(4, 4, 2 * BCD), 256>>>(Fg, Fx);

    ffth_fwd<<<dim3(16, 2 * BCD), blk>>>(Fg, Fx, Gg, Gx, fg, fx, vp);

    var_fin<<<BCD * Hh / 256, 256>>>(vp, rsq);

    scores_tc<<<dim3(4, 4, BCD), 256, 16 * SSZ * 2>>>(Gg, Gx, rsq, S);

    ffth_inv<<<dim3(16, BCD), blk>>>(S, T);

    irfft_add_tc<<<dim3(8, 4, BCD), 256>>>(T, x, rb);

    ln_kernel<<<Bb * 1020, 256, LN_SMEM>>>(rb, gamma, beta, out);
}